// round 5
// baseline (speedup 1.0000x reference)
#include <cuda_runtime.h>
#include <cstdint>

#define BB 2048
#define LL 2048
#define CS 64
#define NCH 32
#define NFWD 31
#define NBWD 31
#define ROWF 16384   // LL*8 floats per emissions row

// ---- scratch (__device__ globals; no allocation allowed) ----
__device__ uint32_t g_w2u[(size_t)LL*4*BB];   // bf16x2 of exp(em), layout [t*4+jp][b]  (64 MiB)
__device__ float g_v[NFWD][8][BB];            // fwd directions
__device__ float g_u[NBWD][8][BB];            // bwd vectors (chunk ch at index ch-1)
__device__ float g_psi[NBWD][BB];             // bwd log-scales
__device__ float g_c0[BB];                    // chunk0 fwd log-scale
__device__ float g_numpart[64][BB];           // numerator partials per 32-step tile
__device__ int   g_len[BB];
__device__ float g_llh[BB];
__device__ int   g_tags64;

// ---- helpers ----
__device__ __forceinline__ int ldtag(const void* t, size_t i, int is64) {
    return is64 ? (int)((const long long*)t)[i] : ((const int*)t)[i];
}
__device__ __forceinline__ unsigned long long pk2(float a, float b) {
    unsigned long long r; asm("mov.b64 %0,{%1,%2};" : "=l"(r) : "f"(a), "f"(b)); return r;
}
__device__ __forceinline__ void up2(unsigned long long v, float& a, float& b) {
    asm("mov.b64 {%0,%1},%2;" : "=f"(a), "=f"(b) : "l"(v));
}
__device__ __forceinline__ unsigned long long fma2(unsigned long long a, unsigned long long b,
                                                   unsigned long long c) {
    unsigned long long d; asm("fma.rn.f32x2 %0,%1,%2,%3;" : "=l"(d) : "l"(a), "l"(b), "l"(c)); return d;
}
__device__ __forceinline__ unsigned long long mul2(unsigned long long a, unsigned long long b) {
    unsigned long long d; asm("mul.rn.f32x2 %0,%1,%2;" : "=l"(d) : "l"(a), "l"(b)); return d;
}
// bf16x2 (u32) -> packed f32x2 (u64); bf16->f32 is exact via <<16
__device__ __forceinline__ unsigned long long bfup(uint32_t w) {
    unsigned long long r;
    asm("{.reg .b32 lo,hi; shl.b32 lo,%1,16; and.b32 hi,%1,0xffff0000U; mov.b64 %0,{lo,hi};}"
        : "=l"(r) : "r"(w));
    return r;
}
__device__ __forceinline__ uint32_t cvtbf2(float lo, float hi) {
    uint32_t r; asm("cvt.rn.satfinite.bf16x2.f32 %0,%1,%2;" : "=r"(r) : "f"(hi), "f"(lo)); return r;
}

// ---- kernel 1: tags dtype detection (int64 vs int32), stateless ----
__global__ void detect_kernel(const int* __restrict__ t32) {
    int lane = threadIdx.x;                       // 32 threads
    int nz = t32[2*lane + 1] | t32[2*(lane+32) + 1];
    unsigned m = __ballot_sync(0xffffffffu, nz != 0);
    if (lane == 0) g_tags64 = (m == 0) ? 1 : 0;
}

// ---- kernel 2: per-row valid length via binary search (valid = prefix, len in [1024,2048]) ----
__global__ void len_kernel(const void* __restrict__ tags) {
    int b = blockIdx.x * 256 + threadIdx.x;
    if (b >= BB) return;
    const int is64 = g_tags64;
    size_t tb = (size_t)b * LL;
    int lo = 1023, hi = 2048;                     // tag[1023] is guaranteed valid
    while (hi - lo > 1) {
        int mid = (lo + hi) >> 1;
        if (ldtag(tags, tb + mid, is64) != 0) lo = mid; else hi = mid;
    }
    g_len[b] = lo + 1;
}

// ---- kernel 3: transpose+exp emissions to [t][jp][b] bf16x2, and numerator partials ----
__global__ __launch_bounds__(256) void prep_kernel(
    const float* __restrict__ em, const float* __restrict__ trans,
    const void* __restrict__ tags)
{
    __shared__ float sh[32][257];    // 32 rows x 256 cols (32 t-steps * 8 tags), padded
    __shared__ float sTr[64];
    __shared__ float shp[32][8];
    int tx = threadIdx.x;
    int t0 = blockIdx.x * 32;        // t-step tile base
    int b0 = blockIdx.y * 32;        // row tile base
    if (tx < 64) sTr[tx] = trans[tx];
    #pragma unroll 4
    for (int k = 0; k < 32; k++)
        sh[k][tx] = em[(size_t)(b0 + k) * ROWF + t0 * 8 + tx];
    __syncthreads();

    // numerator partials: thread (r, sub) handles row r, steps [t0+4*sub, t0+4*sub+4)
    const int is64 = g_tags64;
    int r = tx >> 3, sub = tx & 7;
    size_t tb = (size_t)(b0 + r) * LL;
    int ts = t0 + sub * 4;
    float part = 0.f;
    int prevtag = (ts >= 1) ? ldtag(tags, tb + ts - 1, is64) : 0;
    #pragma unroll
    for (int i = 0; i < 4; i++) {
        int t = ts + i;
        int tg = ldtag(tags, tb + t, is64);
        if (t >= 1 && tg != 0) {
            int s1 = tg - 1, sp = prevtag - 1;
            part += sTr[sp * 8 + s1] + sh[r][(t - t0) * 8 + s1];
        }
        prevtag = tg;
    }
    shp[r][sub] = part;
    __syncthreads();
    if (tx < 32) {
        float s = 0.f;
        #pragma unroll
        for (int j = 0; j < 8; j++) s += shp[tx][j];
        g_numpart[blockIdx.x][b0 + tx] = s;
    }

    // transposed exp write: 32 t-steps * 4 jp * 32 b bf16x2 values
    #pragma unroll
    for (int it = 0; it < 16; it++) {
        int e = it * 256 + tx;
        int bo = e & 31;
        int cj = e >> 5;             // 0..127
        int lt = cj >> 2, jp = cj & 3;
        float lo = __expf(sh[bo][lt * 8 + jp * 2]);
        float hi = __expf(sh[bo][lt * 8 + jp * 2 + 1]);
        g_w2u[((size_t)(t0 + lt) * 4 + jp) * BB + b0 + bo] = cvtbf2(lo, hi);
    }
}

// ---- kernel 4: chunked fwd/bwd passes, f32x2 matvecs, coalesced w loads ----
__global__ __launch_bounds__(128) void pass_kernel(
    const float* __restrict__ em, const float* __restrict__ trans,
    const float* __restrict__ st, const float* __restrict__ en)
{
    __shared__ ulonglong2 sEf[16];  // sEf[2k+h] = (pack(E[k][4h],E[k][4h+1]), pack(E[k][4h+2],E[k][4h+3]))
    __shared__ ulonglong2 sEb[16];  // sEb[2j+h] = (pack(E[4h][j],E[4h+1][j]), pack(E[4h+2][j],E[4h+3][j]))
    __shared__ float sSt[8], sEn[8];
    int tx = threadIdx.x;
    if (tx < 16) {
        int k = tx >> 1, h = tx & 1;
        float a0 = __expf(trans[k*8 + h*4 + 0]);
        float a1 = __expf(trans[k*8 + h*4 + 1]);
        float a2 = __expf(trans[k*8 + h*4 + 2]);
        float a3 = __expf(trans[k*8 + h*4 + 3]);
        ulonglong2 v; v.x = pk2(a0, a1); v.y = pk2(a2, a3);
        sEf[tx] = v;
    } else if (tx < 32) {
        int u = tx - 16; int j = u >> 1, h = u & 1;
        float a0 = __expf(trans[(h*4 + 0)*8 + j]);
        float a1 = __expf(trans[(h*4 + 1)*8 + j]);
        float a2 = __expf(trans[(h*4 + 2)*8 + j]);
        float a3 = __expf(trans[(h*4 + 3)*8 + j]);
        ulonglong2 v; v.x = pk2(a0, a1); v.y = pk2(a2, a3);
        sEb[u] = v;
    } else if (tx < 40) {
        sSt[tx - 32] = st[tx - 32]; sEn[tx - 32] = en[tx - 32];
    }
    __syncthreads();

    int tid = blockIdx.x * 128 + tx;
    if (tid < NFWD * BB) {
        // ---------- forward ----------
        int ch = tid / BB, b = tid % BB;          // lanes: consecutive b -> coalesced
        int len = g_len[b];
        float p[8]; float c = 0.f;
        int tbase, cnt;
        if (ch == 0) {
            float a[8], m = -1e30f;
            #pragma unroll
            for (int j = 0; j < 8; j++) { a[j] = sSt[j] + em[(size_t)b * ROWF + j]; m = fmaxf(m, a[j]); }
            float S = 0.f;
            #pragma unroll
            for (int j = 0; j < 8; j++) { p[j] = __expf(a[j] - m); S += p[j]; }
            float rS = __frcp_rn(S);
            #pragma unroll
            for (int j = 0; j < 8; j++) p[j] *= rS;
            c = m + __logf(S);
            tbase = 1; cnt = min(len, CS) - 1;    // t = 1..63
        } else {
            #pragma unroll
            for (int j = 0; j < 8; j++) p[j] = 0.125f;
            tbase = ch * CS;
            cnt = max(0, min(len - tbase, CS));
        }
        int wmax = __reduce_max_sync(0xffffffffu, cnt);
        const uint32_t* wp = g_w2u + (size_t)tbase * 4 * BB + b;
        for (int i = 0; i < wmax; i++) {
            uint32_t w0 = wp[0], w1 = wp[BB], w2 = wp[2*BB], w3 = wp[3*BB];
            wp += 4 * BB;
            if (i < cnt) {
                unsigned long long q01 = 0, q23 = 0, q45 = 0, q67 = 0;
                #pragma unroll
                for (int k = 0; k < 8; k++) {
                    unsigned long long pk = pk2(p[k], p[k]);
                    ulonglong2 e0 = sEf[2*k], e1 = sEf[2*k + 1];
                    q01 = fma2(pk, e0.x, q01); q23 = fma2(pk, e0.y, q23);
                    q45 = fma2(pk, e1.x, q45); q67 = fma2(pk, e1.y, q67);
                }
                q01 = mul2(q01, bfup(w0)); q23 = mul2(q23, bfup(w1));
                q45 = mul2(q45, bfup(w2)); q67 = mul2(q67, bfup(w3));
                up2(q01, p[0], p[1]); up2(q23, p[2], p[3]);
                up2(q45, p[4], p[5]); up2(q67, p[6], p[7]);
            }
            if ((i & 7) == 7) {   // deferred normalization (scale-semantics preserving)
                float S = ((p[0]+p[1]) + (p[2]+p[3])) + ((p[4]+p[5]) + (p[6]+p[7]));
                float rS = __frcp_rn(S);
                #pragma unroll
                for (int j = 0; j < 8; j++) p[j] *= rS;
                if (ch == 0) c += __logf(S);
            }
        }
        {
            float S = ((p[0]+p[1]) + (p[2]+p[3])) + ((p[4]+p[5]) + (p[6]+p[7]));
            float rS = __frcp_rn(S);
            #pragma unroll
            for (int j = 0; j < 8; j++) p[j] *= rS;
            if (ch == 0) { c += __logf(S); g_c0[b] = c; }
        }
        #pragma unroll
        for (int j = 0; j < 8; j++) g_v[ch][j][b] = p[j];
    } else if (tid < (NFWD + NBWD) * BB) {
        // ---------- backward ----------
        int idx = tid - NFWD * BB;
        int ch = idx / BB + 1, b = idx % BB;      // ch in 1..31
        int len = g_len[b];
        int tbase = ch * CS;
        float r[8]; float psi = 0.f;
        if (ch == NCH - 1) {
            #pragma unroll
            for (int j = 0; j < 8; j++) r[j] = __expf(sEn[j]);
        } else {
            #pragma unroll
            for (int j = 0; j < 8; j++) r[j] = 1.0f;
        }
        int istart = max(0, min(tbase + CS - len, CS));   // first active iteration
        int imin = __reduce_min_sync(0xffffffffu, istart);
        const uint32_t* wp = g_w2u + (size_t)(tbase + CS - 1 - imin) * 4 * BB + b;
        for (int i = imin; i < CS; i++) {
            uint32_t w0 = wp[0], w1 = wp[BB], w2 = wp[2*BB], w3 = wp[3*BB];
            wp -= 4 * BB;
            if (i >= istart) {
                unsigned long long g01 = mul2(pk2(r[0], r[1]), bfup(w0));
                unsigned long long g23 = mul2(pk2(r[2], r[3]), bfup(w1));
                unsigned long long g45 = mul2(pk2(r[4], r[5]), bfup(w2));
                unsigned long long g67 = mul2(pk2(r[6], r[7]), bfup(w3));
                float g[8];
                up2(g01, g[0], g[1]); up2(g23, g[2], g[3]);
                up2(g45, g[4], g[5]); up2(g67, g[6], g[7]);
                unsigned long long n01 = 0, n23 = 0, n45 = 0, n67 = 0;
                #pragma unroll
                for (int j = 0; j < 8; j++) {
                    unsigned long long gk = pk2(g[j], g[j]);
                    ulonglong2 e0 = sEb[2*j], e1 = sEb[2*j + 1];
                    n01 = fma2(gk, e0.x, n01); n23 = fma2(gk, e0.y, n23);
                    n45 = fma2(gk, e1.x, n45); n67 = fma2(gk, e1.y, n67);
                }
                up2(n01, r[0], r[1]); up2(n23, r[2], r[3]);
                up2(n45, r[4], r[5]); up2(n67, r[6], r[7]);
            }
            if ((i & 7) == 7) {
                float S = ((r[0]+r[1]) + (r[2]+r[3])) + ((r[4]+r[5]) + (r[6]+r[7]));
                float rS = __frcp_rn(S);
                #pragma unroll
                for (int j = 0; j < 8; j++) r[j] *= rS;
                psi += __logf(S);     // (r,psi) semantics preserved even for inactive lanes
            }
        }
        float S = ((r[0]+r[1]) + (r[2]+r[3])) + ((r[4]+r[5]) + (r[6]+r[7]));
        float rS = __frcp_rn(S);
        #pragma unroll
        for (int j = 0; j < 8; j++) r[j] *= rS;
        psi += __logf(S);
        #pragma unroll
        for (int j = 0; j < 8; j++) g_u[ch - 1][j][b] = r[j];
        g_psi[ch - 1][b] = psi;
    }
}

// ---- kernel 5: combine per-row ----
__global__ void combine_kernel(const float* __restrict__ em, const float* __restrict__ st,
                               const float* __restrict__ en, const void* __restrict__ tags)
{
    int b = blockIdx.x * 128 + threadIdx.x;
    if (b >= BB) return;
    const int is64 = g_tags64;
    int len = g_len[b];
    int s0 = ldtag(tags, (size_t)b * LL, is64) - 1;
    int sl = ldtag(tags, (size_t)b * LL + len - 1, is64) - 1;
    float num = st[s0] + em[(size_t)b * ROWF + s0] + en[sl];
    #pragma unroll 8
    for (int k = 0; k < 64; k++) num += g_numpart[k][b];

    float d[8];
    #pragma unroll
    for (int j = 0; j < 8; j++) d[j] = g_v[0][j][b];
    float denom = g_c0[b];
    for (int k = 1; k <= NCH - 2; k++) {
        if (len <= k * CS) break;                 // chunk k (and all later interior) empty
        float dot = 0.f;
        #pragma unroll
        for (int j = 0; j < 8; j++) dot += d[j] * g_u[k - 1][j][b];
        denom += g_psi[k - 1][b] + __logf(dot);
        #pragma unroll
        for (int j = 0; j < 8; j++) d[j] = g_v[k][j][b];
    }
    float dot = 0.f;
    #pragma unroll
    for (int j = 0; j < 8; j++) dot += d[j] * g_u[NBWD - 1][j][b];
    denom += g_psi[NBWD - 1][b] + __logf(dot);
    g_llh[b] = num - denom;
}

// ---- kernel 6: mean reduce ----
__global__ void reduce_kernel(float* __restrict__ out) {
    __shared__ float sw[32];
    int tx = threadIdx.x;                         // 1024 threads
    float s = g_llh[tx] + g_llh[tx + 1024];
    #pragma unroll
    for (int o = 16; o > 0; o >>= 1) s += __shfl_xor_sync(0xffffffffu, s, o);
    if ((tx & 31) == 0) sw[tx >> 5] = s;
    __syncthreads();
    if (tx < 32) {
        float v = sw[tx];
        #pragma unroll
        for (int o = 16; o > 0; o >>= 1) v += __shfl_xor_sync(0xffffffffu, v, o);
        if (tx == 0) out[0] = -v / (float)BB;
    }
}

extern "C" void kernel_launch(void* const* d_in, const int* in_sizes, int n_in,
                              void* d_out, int out_size) {
    const float* em    = (const float*)d_in[0];
    const float* trans = (const float*)d_in[1];
    const float* st    = (const float*)d_in[2];
    const float* en    = (const float*)d_in[3];
    const void*  tags  = d_in[4];
    (void)in_sizes; (void)n_in; (void)out_size;

    detect_kernel<<<1, 32>>>((const int*)tags);
    len_kernel<<<8, 256>>>(tags);
    prep_kernel<<<dim3(64, 64), 256>>>(em, trans, tags);
    pass_kernel<<<(NFWD + NBWD) * BB / 128, 128>>>(em, trans, st, en);
    combine_kernel<<<16, 128>>>(em, st, en, tags);
    reduce_kernel<<<1, 1024>>>((float*)d_out);
}

// round 9
// speedup vs baseline: 1.2451x; 1.2451x over previous
#include <cuda_runtime.h>
#include <cstdint>

#define BB 2048
#define LL 2048
#define ROWF 16384          // LL*8 floats per emissions row
#define CS 32               // steps per chunk
#define NCH 64              // chunks per row

// ---- scratch (__device__ globals; allocation-free rule) ----
__device__ float g_v[NCH][8][BB];     // fwd directions per chunk
__device__ float g_u[NCH][8][BB];     // bwd vectors per chunk (u[0] unused)
__device__ float g_psi[NCH][BB];      // bwd log-scales
__device__ float g_c0[BB];            // chunk0 fwd log-scale
__device__ float g_nump[NCH][BB];     // numerator partials per chunk
__device__ int   g_len[BB];
__device__ float g_llh[BB];
__device__ int   g_tags64;

// ---- helpers ----
__device__ __forceinline__ int ldtag(const void* t, size_t i, int is64) {
    return is64 ? (int)((const long long*)t)[i] : ((const int*)t)[i];
}
__device__ __forceinline__ unsigned long long pk2(float a, float b) {
    unsigned long long r; asm("mov.b64 %0,{%1,%2};" : "=l"(r) : "f"(a), "f"(b)); return r;
}
__device__ __forceinline__ void up2(unsigned long long v, float& a, float& b) {
    asm("mov.b64 {%0,%1},%2;" : "=f"(a), "=f"(b) : "l"(v));
}
__device__ __forceinline__ unsigned long long fma2(unsigned long long a, unsigned long long b,
                                                   unsigned long long c) {
    unsigned long long d; asm("fma.rn.f32x2 %0,%1,%2,%3;" : "=l"(d) : "l"(a), "l"(b), "l"(c)); return d;
}
__device__ __forceinline__ unsigned long long mul2(unsigned long long a, unsigned long long b) {
    unsigned long long d; asm("mul.rn.f32x2 %0,%1,%2;" : "=l"(d) : "l"(a), "l"(b)); return d;
}
// bf16x2 (u32) -> packed f32x2 (u64); exact via <<16
__device__ __forceinline__ unsigned long long bfup(uint32_t w) {
    unsigned long long r;
    asm("{.reg .b32 lo,hi; shl.b32 lo,%1,16; and.b32 hi,%1,0xffff0000U; mov.b64 %0,{lo,hi};}"
        : "=l"(r) : "r"(w));
    return r;
}
__device__ __forceinline__ uint32_t cvtbf2(float lo, float hi) {
    uint32_t r; asm("cvt.rn.satfinite.bf16x2.f32 %0,%1,%2;" : "=r"(r) : "f"(hi), "f"(lo)); return r;
}

// ---- kernel 1: tags dtype detection ----
__global__ void detect_kernel(const int* __restrict__ t32) {
    int lane = threadIdx.x;                       // 32 threads
    int nz = t32[2*lane + 1] | t32[2*(lane+32) + 1];
    unsigned m = __ballot_sync(0xffffffffu, nz != 0);
    if (lane == 0) g_tags64 = (m == 0) ? 1 : 0;
}

// ---- kernel 2: per-row valid length (valid = prefix, len in [1024,2048]) ----
__global__ void len_kernel(const void* __restrict__ tags) {
    int b = blockIdx.x * 256 + threadIdx.x;
    if (b >= BB) return;
    const int is64 = g_tags64;
    size_t tb = (size_t)b * LL;
    int lo = 1023, hi = 2048;
    while (hi - lo > 1) {
        int mid = (lo + hi) >> 1;
        if (ldtag(tags, tb + mid, is64) != 0) lo = mid; else hi = mid;
    }
    g_len[b] = lo + 1;
}

// ---- kernel 3: fused chunk pass (stage tile once; fwd+bwd+numerator) ----
__global__ __launch_bounds__(64) void crf_pass(
    const float* __restrict__ em, const float* __restrict__ trans,
    const float* __restrict__ st, const float* __restrict__ en,
    const void* __restrict__ tags)
{
    __shared__ uint32_t sW[64][132];   // bf16x2 exp(em): [row][step*4+jp]; 528B stride (16B aligned)
    __shared__ uint8_t  sTag[64][40];  // tag values (0..8) per [row][step]
    __shared__ ulonglong2 sEf[16];     // fwd: sEf[2k+h] = pack(E[k][4h..4h+3])
    __shared__ ulonglong2 sEb[16];     // bwd: sEb[2j+h] = pack(E[4h..4h+3][j])
    __shared__ float sTr[64], sSt[8], sEn[8];

    const int tx = threadIdx.x;        // 0..63
    const int ch = blockIdx.y;         // 0..63
    const int b0 = blockIdx.x << 6;    // 64 rows per block
    const int tbase = ch << 5;         // 32 steps per chunk
    const int is64 = g_tags64;

    // constants
    sTr[tx] = trans[tx];
    if (tx < 16) {
        int k = tx >> 1, h = tx & 1;
        float a0 = __expf(trans[k*8 + h*4 + 0]);
        float a1 = __expf(trans[k*8 + h*4 + 1]);
        float a2 = __expf(trans[k*8 + h*4 + 2]);
        float a3 = __expf(trans[k*8 + h*4 + 3]);
        ulonglong2 v; v.x = pk2(a0, a1); v.y = pk2(a2, a3);
        sEf[tx] = v;
    } else if (tx < 32) {
        int u = tx - 16; int j = u >> 1, h = u & 1;
        float a0 = __expf(trans[(h*4 + 0)*8 + j]);
        float a1 = __expf(trans[(h*4 + 1)*8 + j]);
        float a2 = __expf(trans[(h*4 + 2)*8 + j]);
        float a3 = __expf(trans[(h*4 + 3)*8 + j]);
        ulonglong2 v; v.x = pk2(a0, a1); v.y = pk2(a2, a3);
        sEb[u] = v;
    } else if (tx < 40) { sSt[tx - 32] = st[tx - 32]; }
    else if (tx < 48)   { sEn[tx - 40] = en[tx - 40]; }

    // ---- stage tags: [row][32 steps] -> u8, coalesced ----
    if (is64) {
        const uint4* tp = (const uint4*)tags;      // 16B = 2 i64 tags; 16 uint4 per row
        #pragma unroll
        for (int it = 0; it < 16; it++) {
            int idx = it * 64 + tx;                // 0..1023
            int row = idx >> 4, v = idx & 15;
            uint4 t = tp[(size_t)(b0 + row) * 1024 + (tbase >> 1) + v];
            sTag[row][v*2]     = (uint8_t)t.x;
            sTag[row][v*2 + 1] = (uint8_t)t.z;
        }
    } else {
        const uint4* tp = (const uint4*)tags;      // 16B = 4 i32 tags; 8 uint4 per row
        #pragma unroll
        for (int it = 0; it < 8; it++) {
            int idx = it * 64 + tx;                // 0..511
            int row = idx >> 3, v = idx & 7;
            uint4 t = tp[(size_t)(b0 + row) * 512 + (tbase >> 2) + v];
            sTag[row][v*4]     = (uint8_t)t.x;
            sTag[row][v*4 + 1] = (uint8_t)t.y;
            sTag[row][v*4 + 2] = (uint8_t)t.z;
            sTag[row][v*4 + 3] = (uint8_t)t.w;
        }
    }

    // ---- stage emissions: coalesced float4 loads, exp -> bf16x2 to SMEM ----
    {
        const float4* em4 = (const float4*)em;
        #pragma unroll 1
        for (int r8 = 0; r8 < 64; r8 += 8) {
            float4 v[8];
            #pragma unroll
            for (int k = 0; k < 8; k++)
                v[k] = em4[(size_t)(b0 + r8 + k) * 4096 + tbase * 2 + tx];
            #pragma unroll
            for (int k = 0; k < 8; k++) {
                float e0 = __expf(v[k].x), e1 = __expf(v[k].y);
                float e2 = __expf(v[k].z), e3 = __expf(v[k].w);
                uint2 w; w.x = cvtbf2(e0, e1); w.y = cvtbf2(e2, e3);
                *(uint2*)&sW[r8 + k][tx * 2] = w;
            }
        }
    }
    __syncthreads();

    // ---- compute: thread tx owns row b0+tx ----
    const int b = b0 + tx;
    const int len = g_len[b];
    int nact = len - tbase; nact = nact < 0 ? 0 : (nact > CS ? CS : nact);
    const int wmax = __reduce_max_sync(0xffffffffu, nact);

    // ================= forward =================
    {
        float p[8]; float c = 0.f, num = 0.f;
        int prev, i0;
        if (ch == 0) {
            const float* emrow = em + (size_t)b * ROWF;
            float a[8], m = -1e30f;
            #pragma unroll
            for (int j = 0; j < 8; j++) { a[j] = sSt[j] + emrow[j]; m = fmaxf(m, a[j]); }
            float S = 0.f;
            #pragma unroll
            for (int j = 0; j < 8; j++) { p[j] = __expf(a[j] - m); S += p[j]; }
            float rS = __frcp_rn(S);
            #pragma unroll
            for (int j = 0; j < 8; j++) p[j] *= rS;
            c = m + __logf(S);
            int s0 = (int)sTag[tx][0] - 1;
            num = sSt[s0] + emrow[s0];
            prev = s0; i0 = 1;
        } else {
            #pragma unroll
            for (int j = 0; j < 8; j++) p[j] = 0.125f;
            prev = ldtag(tags, (size_t)b * LL + tbase - 1, is64) - 1;
            i0 = 0;
        }
        for (int i = i0; i < wmax; i++) {
            uint4 w4 = *(const uint4*)&sW[tx][i << 2];
            if (i < nact) {
                int s1 = (int)sTag[tx][i] - 1;
                uint32_t wsel = (s1 & 4) ? ((s1 & 2) ? w4.w : w4.z)
                                         : ((s1 & 2) ? w4.y : w4.x);
                float wf = (s1 & 1) ? __uint_as_float(wsel & 0xffff0000u)
                                    : __uint_as_float(wsel << 16);
                num += sTr[(prev << 3) + s1] + __logf(wf);
                prev = s1;
                unsigned long long q01 = 0, q23 = 0, q45 = 0, q67 = 0;
                #pragma unroll
                for (int k = 0; k < 8; k++) {
                    unsigned long long pk = pk2(p[k], p[k]);
                    ulonglong2 e0 = sEf[2*k], e1 = sEf[2*k + 1];
                    q01 = fma2(pk, e0.x, q01); q23 = fma2(pk, e0.y, q23);
                    q45 = fma2(pk, e1.x, q45); q67 = fma2(pk, e1.y, q67);
                }
                q01 = mul2(q01, bfup(w4.x)); q23 = mul2(q23, bfup(w4.y));
                q45 = mul2(q45, bfup(w4.z)); q67 = mul2(q67, bfup(w4.w));
                up2(q01, p[0], p[1]); up2(q23, p[2], p[3]);
                up2(q45, p[4], p[5]); up2(q67, p[6], p[7]);
            }
            if ((i & 7) == 7) {   // deferred normalization
                float S = ((p[0]+p[1]) + (p[2]+p[3])) + ((p[4]+p[5]) + (p[6]+p[7]));
                float rS = __frcp_rn(S);
                #pragma unroll
                for (int j = 0; j < 8; j++) p[j] *= rS;
                if (ch == 0) c += __logf(S);
            }
        }
        {   // final norm (double-norm harmless: log(1)=0)
            float S = ((p[0]+p[1]) + (p[2]+p[3])) + ((p[4]+p[5]) + (p[6]+p[7]));
            float rS = __frcp_rn(S);
            #pragma unroll
            for (int j = 0; j < 8; j++) p[j] *= rS;
            if (ch == 0) { c += __logf(S); g_c0[b] = c; }
        }
        #pragma unroll
        for (int j = 0; j < 8; j++) g_v[ch][j][b] = p[j];
        g_nump[ch][b] = num;
    }

    // ================= backward =================
    if (ch > 0) {
        float r[8]; float psi = 0.f;
        if (ch == NCH - 1) {
            #pragma unroll
            for (int j = 0; j < 8; j++) r[j] = __expf(sEn[j]);
        } else {
            #pragma unroll
            for (int j = 0; j < 8; j++) r[j] = 1.0f;
        }
        for (int i = wmax - 1; i >= 0; i--) {
            uint4 w4 = *(const uint4*)&sW[tx][i << 2];
            if (i < nact) {
                unsigned long long g01 = mul2(pk2(r[0], r[1]), bfup(w4.x));
                unsigned long long g23 = mul2(pk2(r[2], r[3]), bfup(w4.y));
                unsigned long long g45 = mul2(pk2(r[4], r[5]), bfup(w4.z));
                unsigned long long g67 = mul2(pk2(r[6], r[7]), bfup(w4.w));
                float g[8];
                up2(g01, g[0], g[1]); up2(g23, g[2], g[3]);
                up2(g45, g[4], g[5]); up2(g67, g[6], g[7]);
                unsigned long long n01 = 0, n23 = 0, n45 = 0, n67 = 0;
                #pragma unroll
                for (int j = 0; j < 8; j++) {
                    unsigned long long gk = pk2(g[j], g[j]);
                    ulonglong2 e0 = sEb[2*j], e1 = sEb[2*j + 1];
                    n01 = fma2(gk, e0.x, n01); n23 = fma2(gk, e0.y, n23);
                    n45 = fma2(gk, e1.x, n45); n67 = fma2(gk, e1.y, n67);
                }
                up2(n01, r[0], r[1]); up2(n23, r[2], r[3]);
                up2(n45, r[4], r[5]); up2(n67, r[6], r[7]);
            }
            if ((i & 7) == 0 && i > 0) {
                float S = ((r[0]+r[1]) + (r[2]+r[3])) + ((r[4]+r[5]) + (r[6]+r[7]));
                float rS = __frcp_rn(S);
                #pragma unroll
                for (int j = 0; j < 8; j++) r[j] *= rS;
                psi += __logf(S);
            }
        }
        {
            float S = ((r[0]+r[1]) + (r[2]+r[3])) + ((r[4]+r[5]) + (r[6]+r[7]));
            float rS = __frcp_rn(S);
            #pragma unroll
            for (int j = 0; j < 8; j++) r[j] *= rS;
            psi += __logf(S);
        }
        #pragma unroll
        for (int j = 0; j < 8; j++) g_u[ch][j][b] = r[j];
        g_psi[ch][b] = psi;
    }
}

// ---- kernel 4: combine per-row ----
__global__ void combine_kernel(const float* __restrict__ en, const void* __restrict__ tags)
{
    int b = blockIdx.x * 128 + threadIdx.x;
    if (b >= BB) return;
    const int is64 = g_tags64;
    int len = g_len[b];
    int sl = ldtag(tags, (size_t)b * LL + len - 1, is64) - 1;
    float num = en[sl];
    #pragma unroll 8
    for (int k = 0; k < NCH; k++) num += g_nump[k][b];

    float d[8];
    #pragma unroll
    for (int j = 0; j < 8; j++) d[j] = g_v[0][j][b];
    float denom = g_c0[b];
    for (int k = 1; k <= NCH - 2; k++) {           // interior chunks (rank-1)
        if (len <= k * CS) break;                  // inactive suffix
        float dot = 0.f;
        #pragma unroll
        for (int j = 0; j < 8; j++) dot += d[j] * g_u[k][j][b];
        denom += g_psi[k][b] + __logf(dot);
        #pragma unroll
        for (int j = 0; j < 8; j++) d[j] = g_v[k][j][b];
    }
    float dot = 0.f;
    #pragma unroll
    for (int j = 0; j < 8; j++) dot += d[j] * g_u[NCH - 1][j][b];
    denom += g_psi[NCH - 1][b] + __logf(dot);
    g_llh[b] = num - denom;
}

// ---- kernel 5: mean reduce ----
__global__ void reduce_kernel(float* __restrict__ out) {
    __shared__ float sw[32];
    int tx = threadIdx.x;                          // 1024 threads
    float s = g_llh[tx] + g_llh[tx + 1024];
    #pragma unroll
    for (int o = 16; o > 0; o >>= 1) s += __shfl_xor_sync(0xffffffffu, s, o);
    if ((tx & 31) == 0) sw[tx >> 5] = s;
    __syncthreads();
    if (tx < 32) {
        float v = sw[tx];
        #pragma unroll
        for (int o = 16; o > 0; o >>= 1) v += __shfl_xor_sync(0xffffffffu, v, o);
        if (tx == 0) out[0] = -v / (float)BB;
    }
}

extern "C" void kernel_launch(void* const* d_in, const int* in_sizes, int n_in,
                              void* d_out, int out_size) {
    const float* em    = (const float*)d_in[0];
    const float* trans = (const float*)d_in[1];
    const float* st    = (const float*)d_in[2];
    const float* en    = (const float*)d_in[3];
    const void*  tags  = d_in[4];
    (void)in_sizes; (void)n_in; (void)out_size;

    detect_kernel<<<1, 32>>>((const int*)tags);
    len_kernel<<<8, 256>>>(tags);
    crf_pass<<<dim3(32, 64), 64>>>(em, trans, st, en, tags);
    combine_kernel<<<16, 128>>>(en, tags);
    reduce_kernel<<<1, 1024>>>((float*)d_out);
}

// round 11
// speedup vs baseline: 2.3859x; 1.9163x over previous
#include <cuda_runtime.h>
#include <cstdint>

#define BB 2048
#define LL 2048
#define ROWF 16384          // LL*8 floats per emissions row
#define CS 32               // steps per chunk
#define NCH 64              // chunks per row

// ---- scratch (__device__ globals; allocation-free rule) ----
__device__ float g_v[NCH][8][BB];     // fwd directions per chunk
__device__ float g_u[NCH][8][BB];     // bwd vectors per chunk (u[0] unused)
__device__ float g_psi[NCH][BB];      // bwd log-scales
__device__ float g_c0[BB];            // chunk0 fwd log-scale
__device__ float g_nump[NCH][BB];     // numerator partials per chunk
__device__ int   g_len[BB];
__device__ float g_llh[BB];
__device__ int   g_tags64;

// ---- helpers ----
__device__ __forceinline__ int ldtag(const void* t, size_t i, int is64) {
    return is64 ? (int)((const long long*)t)[i] : ((const int*)t)[i];
}
__device__ __forceinline__ unsigned long long pk2(float a, float b) {
    unsigned long long r; asm("mov.b64 %0,{%1,%2};" : "=l"(r) : "f"(a), "f"(b)); return r;
}
__device__ __forceinline__ void up2(unsigned long long v, float& a, float& b) {
    asm("mov.b64 {%0,%1},%2;" : "=f"(a), "=f"(b) : "l"(v));
}
__device__ __forceinline__ unsigned long long fma2(unsigned long long a, unsigned long long b,
                                                   unsigned long long c) {
    unsigned long long d; asm("fma.rn.f32x2 %0,%1,%2,%3;" : "=l"(d) : "l"(a), "l"(b), "l"(c)); return d;
}
__device__ __forceinline__ unsigned long long mul2(unsigned long long a, unsigned long long b) {
    unsigned long long d; asm("mul.rn.f32x2 %0,%1,%2;" : "=l"(d) : "l"(a), "l"(b)); return d;
}
// bf16x2 (u32) -> packed f32x2 (u64); exact via <<16
__device__ __forceinline__ unsigned long long bfup(uint32_t w) {
    unsigned long long r;
    asm("{.reg .b32 lo,hi; shl.b32 lo,%1,16; and.b32 hi,%1,0xffff0000U; mov.b64 %0,{lo,hi};}"
        : "=l"(r) : "r"(w));
    return r;
}
__device__ __forceinline__ uint32_t cvtbf2(float lo, float hi) {
    uint32_t r; asm("cvt.rn.satfinite.bf16x2.f32 %0,%1,%2;" : "=r"(r) : "f"(hi), "f"(lo)); return r;
}

// ---- kernel 1: tags dtype detection ----
__global__ void detect_kernel(const int* __restrict__ t32) {
    int lane = threadIdx.x;                       // 32 threads
    int nz = t32[2*lane + 1] | t32[2*(lane+32) + 1];
    unsigned m = __ballot_sync(0xffffffffu, nz != 0);
    if (lane == 0) g_tags64 = (m == 0) ? 1 : 0;
}

// ---- kernel 2: per-row valid length (valid = prefix, len in [1024,2048]) ----
__global__ void len_kernel(const void* __restrict__ tags) {
    int b = blockIdx.x * 256 + threadIdx.x;
    if (b >= BB) return;
    const int is64 = g_tags64;
    size_t tb = (size_t)b * LL;
    int lo = 1023, hi = 2048;
    while (hi - lo > 1) {
        int mid = (lo + hi) >> 1;
        if (ldtag(tags, tb + mid, is64) != 0) lo = mid; else hi = mid;
    }
    g_len[b] = lo + 1;
}

// ---- kernel 3: fused chunk pass (stage tile once; fwd+bwd+numerator) ----
__global__ __launch_bounds__(64) void crf_pass(
    const float* __restrict__ em, const float* __restrict__ trans,
    const float* __restrict__ st, const float* __restrict__ en,
    const void* __restrict__ tags)
{
    __shared__ uint32_t sW[64][132];   // bf16x2 exp(em): [row][step*4+jp]; 528B stride (16B aligned)
    __shared__ uint8_t  sTag[64][40];  // tag values (0..8) per [row][step]
    __shared__ ulonglong2 sEf[16];     // fwd: sEf[2k+h] = pack(E[k][4h..4h+3])
    __shared__ ulonglong2 sEb[16];     // bwd: sEb[2j+h] = pack(E[4h..4h+3][j])
    __shared__ float sTr[64], sSt[8], sEn[8];

    const int tx = threadIdx.x;        // 0..63
    const int ch = blockIdx.y;         // 0..63
    const int b0 = blockIdx.x << 6;    // 64 rows per block
    const int tbase = ch << 5;         // 32 steps per chunk
    const int is64 = g_tags64;

    // constants
    sTr[tx] = trans[tx];
    if (tx < 16) {
        int k = tx >> 1, h = tx & 1;
        float a0 = __expf(trans[k*8 + h*4 + 0]);
        float a1 = __expf(trans[k*8 + h*4 + 1]);
        float a2 = __expf(trans[k*8 + h*4 + 2]);
        float a3 = __expf(trans[k*8 + h*4 + 3]);
        ulonglong2 v; v.x = pk2(a0, a1); v.y = pk2(a2, a3);
        sEf[tx] = v;
    } else if (tx < 32) {
        int u = tx - 16; int j = u >> 1, h = u & 1;
        float a0 = __expf(trans[(h*4 + 0)*8 + j]);
        float a1 = __expf(trans[(h*4 + 1)*8 + j]);
        float a2 = __expf(trans[(h*4 + 2)*8 + j]);
        float a3 = __expf(trans[(h*4 + 3)*8 + j]);
        ulonglong2 v; v.x = pk2(a0, a1); v.y = pk2(a2, a3);
        sEb[u] = v;
    } else if (tx < 40) { sSt[tx - 32] = st[tx - 32]; }
    else if (tx < 48)   { sEn[tx - 40] = en[tx - 40]; }

    // ---- stage tags: [row][32 steps] -> u8, coalesced ----
    if (is64) {
        const uint4* tp = (const uint4*)tags;      // 16B = 2 i64 tags; 16 uint4 per row
        #pragma unroll
        for (int it = 0; it < 16; it++) {
            int idx = it * 64 + tx;                // 0..1023
            int row = idx >> 4, v = idx & 15;
            uint4 t = tp[(size_t)(b0 + row) * 1024 + (tbase >> 1) + v];
            sTag[row][v*2]     = (uint8_t)t.x;
            sTag[row][v*2 + 1] = (uint8_t)t.z;
        }
    } else {
        const uint4* tp = (const uint4*)tags;      // 16B = 4 i32 tags; 8 uint4 per row
        #pragma unroll
        for (int it = 0; it < 8; it++) {
            int idx = it * 64 + tx;                // 0..511
            int row = idx >> 3, v = idx & 7;
            uint4 t = tp[(size_t)(b0 + row) * 512 + (tbase >> 2) + v];
            sTag[row][v*4]     = (uint8_t)t.x;
            sTag[row][v*4 + 1] = (uint8_t)t.y;
            sTag[row][v*4 + 2] = (uint8_t)t.z;
            sTag[row][v*4 + 3] = (uint8_t)t.w;
        }
    }

    // ---- stage emissions: coalesced float4 loads, exp -> bf16x2 to SMEM ----
    {
        const float4* em4 = (const float4*)em;
        #pragma unroll 1
        for (int r8 = 0; r8 < 64; r8 += 8) {
            float4 v[8];
            #pragma unroll
            for (int k = 0; k < 8; k++)
                v[k] = em4[(size_t)(b0 + r8 + k) * 4096 + tbase * 2 + tx];
            #pragma unroll
            for (int k = 0; k < 8; k++) {
                float e0 = __expf(v[k].x), e1 = __expf(v[k].y);
                float e2 = __expf(v[k].z), e3 = __expf(v[k].w);
                uint2 w; w.x = cvtbf2(e0, e1); w.y = cvtbf2(e2, e3);
                *(uint2*)&sW[r8 + k][tx * 2] = w;
            }
        }
    }
    __syncthreads();

    // ---- compute: thread tx owns row b0+tx ----
    const int b = b0 + tx;
    const int len = g_len[b];
    int nact = len - tbase; nact = nact < 0 ? 0 : (nact > CS ? CS : nact);
    const int wmax = __reduce_max_sync(0xffffffffu, nact);

    // ================= forward =================
    {
        float p[8]; float c = 0.f, num = 0.f;
        int prev, i0;
        if (ch == 0) {
            const float* emrow = em + (size_t)b * ROWF;
            float a[8], m = -1e30f;
            #pragma unroll
            for (int j = 0; j < 8; j++) { a[j] = sSt[j] + emrow[j]; m = fmaxf(m, a[j]); }
            float S = 0.f;
            #pragma unroll
            for (int j = 0; j < 8; j++) { p[j] = __expf(a[j] - m); S += p[j]; }
            float rS = __frcp_rn(S);
            #pragma unroll
            for (int j = 0; j < 8; j++) p[j] *= rS;
            c = m + __logf(S);
            int s0 = (int)sTag[tx][0] - 1;
            num = sSt[s0] + emrow[s0];
            prev = s0; i0 = 1;
        } else {
            #pragma unroll
            for (int j = 0; j < 8; j++) p[j] = 0.125f;
            prev = ldtag(tags, (size_t)b * LL + tbase - 1, is64) - 1;
            i0 = 0;
        }
        for (int i = i0; i < wmax; i++) {
            uint4 w4 = *(const uint4*)&sW[tx][i << 2];
            if (i < nact) {
                int s1 = (int)sTag[tx][i] - 1;
                uint32_t wsel = (s1 & 4) ? ((s1 & 2) ? w4.w : w4.z)
                                         : ((s1 & 2) ? w4.y : w4.x);
                float wf = (s1 & 1) ? __uint_as_float(wsel & 0xffff0000u)
                                    : __uint_as_float(wsel << 16);
                num += sTr[(prev << 3) + s1] + __logf(wf);
                prev = s1;
                unsigned long long q01 = 0, q23 = 0, q45 = 0, q67 = 0;
                #pragma unroll
                for (int k = 0; k < 8; k++) {
                    unsigned long long pk = pk2(p[k], p[k]);
                    ulonglong2 e0 = sEf[2*k], e1 = sEf[2*k + 1];
                    q01 = fma2(pk, e0.x, q01); q23 = fma2(pk, e0.y, q23);
                    q45 = fma2(pk, e1.x, q45); q67 = fma2(pk, e1.y, q67);
                }
                q01 = mul2(q01, bfup(w4.x)); q23 = mul2(q23, bfup(w4.y));
                q45 = mul2(q45, bfup(w4.z)); q67 = mul2(q67, bfup(w4.w));
                up2(q01, p[0], p[1]); up2(q23, p[2], p[3]);
                up2(q45, p[4], p[5]); up2(q67, p[6], p[7]);
            }
            if ((i & 7) == 7) {   // deferred normalization
                float S = ((p[0]+p[1]) + (p[2]+p[3])) + ((p[4]+p[5]) + (p[6]+p[7]));
                float rS = __frcp_rn(S);
                #pragma unroll
                for (int j = 0; j < 8; j++) p[j] *= rS;
                if (ch == 0) c += __logf(S);
            }
        }
        {   // final norm (double-norm harmless: log(1)=0)
            float S = ((p[0]+p[1]) + (p[2]+p[3])) + ((p[4]+p[5]) + (p[6]+p[7]));
            float rS = __frcp_rn(S);
            #pragma unroll
            for (int j = 0; j < 8; j++) p[j] *= rS;
            if (ch == 0) { c += __logf(S); g_c0[b] = c; }
        }
        #pragma unroll
        for (int j = 0; j < 8; j++) g_v[ch][j][b] = p[j];
        g_nump[ch][b] = num;
    }

    // ================= backward =================
    if (ch > 0) {
        float r[8]; float psi = 0.f;
        if (ch == NCH - 1) {
            #pragma unroll
            for (int j = 0; j < 8; j++) r[j] = __expf(sEn[j]);
        } else {
            #pragma unroll
            for (int j = 0; j < 8; j++) r[j] = 1.0f;
        }
        for (int i = wmax - 1; i >= 0; i--) {
            uint4 w4 = *(const uint4*)&sW[tx][i << 2];
            if (i < nact) {
                unsigned long long g01 = mul2(pk2(r[0], r[1]), bfup(w4.x));
                unsigned long long g23 = mul2(pk2(r[2], r[3]), bfup(w4.y));
                unsigned long long g45 = mul2(pk2(r[4], r[5]), bfup(w4.z));
                unsigned long long g67 = mul2(pk2(r[6], r[7]), bfup(w4.w));
                float g[8];
                up2(g01, g[0], g[1]); up2(g23, g[2], g[3]);
                up2(g45, g[4], g[5]); up2(g67, g[6], g[7]);
                unsigned long long n01 = 0, n23 = 0, n45 = 0, n67 = 0;
                #pragma unroll
                for (int j = 0; j < 8; j++) {
                    unsigned long long gk = pk2(g[j], g[j]);
                    ulonglong2 e0 = sEb[2*j], e1 = sEb[2*j + 1];
                    n01 = fma2(gk, e0.x, n01); n23 = fma2(gk, e0.y, n23);
                    n45 = fma2(gk, e1.x, n45); n67 = fma2(gk, e1.y, n67);
                }
                up2(n01, r[0], r[1]); up2(n23, r[2], r[3]);
                up2(n45, r[4], r[5]); up2(n67, r[6], r[7]);
            }
            if ((i & 7) == 0 && i > 0) {
                float S = ((r[0]+r[1]) + (r[2]+r[3])) + ((r[4]+r[5]) + (r[6]+r[7]));
                float rS = __frcp_rn(S);
                #pragma unroll
                for (int j = 0; j < 8; j++) r[j] *= rS;
                psi += __logf(S);
            }
        }
        {
            float S = ((r[0]+r[1]) + (r[2]+r[3])) + ((r[4]+r[5]) + (r[6]+r[7]));
            float rS = __frcp_rn(S);
            #pragma unroll
            for (int j = 0; j < 8; j++) r[j] *= rS;
            psi += __logf(S);
        }
        #pragma unroll
        for (int j = 0; j < 8; j++) g_u[ch][j][b] = r[j];
        g_psi[ch][b] = psi;
    }
}

// ---- kernel 4: combine per-row, one WARP per row (terms are independent!) ----
// denom = c0 + sum_{k=1..62, k*32<len} [psi[k] + log(v[k-1].u[k])]
//            + psi[63] + log(v[k_last].u[63]),  k_last = min(62, (len-1)>>5)
__global__ __launch_bounds__(256) void combine_kernel(
    const float* __restrict__ en, const void* __restrict__ tags)
{
    int b = blockIdx.x * 8 + (threadIdx.x >> 5);   // warp -> row
    int lane = threadIdx.x & 31;
    const int len = g_len[b];

    // numerator partials (coalesced-ish; all L2-resident)
    float acc = g_nump[lane][b] + g_nump[lane + 32][b];

    // interior terms: lane handles k = lane+1 and k = lane+33 (k <= 62)
    #pragma unroll
    for (int h = 0; h < 2; h++) {
        int k = lane + 1 + h * 32;
        if (k <= NCH - 2 && k * CS < len) {
            float dot = 0.f;
            #pragma unroll
            for (int j = 0; j < 8; j++) dot += g_v[k - 1][j][b] * g_u[k][j][b];
            acc -= g_psi[k][b] + __logf(dot);      // denom enters negatively
        }
    }

    if (lane == 0) {
        const int is64 = g_tags64;
        int sl = ldtag(tags, (size_t)b * LL + len - 1, is64) - 1;
        int k_last = (len - 1) >> 5; if (k_last > NCH - 2) k_last = NCH - 2;
        float dot = 0.f;
        #pragma unroll
        for (int j = 0; j < 8; j++) dot += g_v[k_last][j][b] * g_u[NCH - 1][j][b];
        acc += en[sl] - g_c0[b] - (g_psi[NCH - 1][b] + __logf(dot));
    }

    #pragma unroll
    for (int o = 16; o > 0; o >>= 1) acc += __shfl_xor_sync(0xffffffffu, acc, o);
    if (lane == 0) g_llh[b] = acc;                 // = num - denom
}

// ---- kernel 5: mean reduce ----
__global__ void reduce_kernel(float* __restrict__ out) {
    __shared__ float sw[32];
    int tx = threadIdx.x;                          // 1024 threads
    float s = g_llh[tx] + g_llh[tx + 1024];
    #pragma unroll
    for (int o = 16; o > 0; o >>= 1) s += __shfl_xor_sync(0xffffffffu, s, o);
    if ((tx & 31) == 0) sw[tx >> 5] = s;
    __syncthreads();
    if (tx < 32) {
        float v = sw[tx];
        #pragma unroll
        for (int o = 16; o > 0; o >>= 1) v += __shfl_xor_sync(0xffffffffu, v, o);
        if (tx == 0) out[0] = -v / (float)BB;
    }
}

extern "C" void kernel_launch(void* const* d_in, const int* in_sizes, int n_in,
                              void* d_out, int out_size) {
    const float* em    = (const float*)d_in[0];
    const float* trans = (const float*)d_in[1];
    const float* st    = (const float*)d_in[2];
    const float* en    = (const float*)d_in[3];
    const void*  tags  = d_in[4];
    (void)in_sizes; (void)n_in; (void)out_size;

    detect_kernel<<<1, 32>>>((const int*)tags);
    len_kernel<<<8, 256>>>(tags);
    crf_pass<<<dim3(32, 64), 64>>>(em, trans, st, en, tags);
    combine_kernel<<<BB / 8, 256>>>(en, tags);
    reduce_kernel<<<1, 1024>>>((float*)d_out);
}

// round 15
// speedup vs baseline: 2.4648x; 1.0331x over previous
#include <cuda_runtime.h>
#include <cstdint>

#define BB 2048
#define LL 2048
#define ROWF 16384          // LL*8 floats per emissions row
#define CS 32               // steps per chunk
#define NCH 64              // chunks per row

// ---- scratch (__device__ globals; allocation-free rule) ----
__device__ float g_v[NCH][8][BB];     // fwd directions per chunk
__device__ float g_u[NCH][8][BB];     // bwd vectors per chunk (u[0] unused)
__device__ float g_psi[NCH][BB];      // bwd log-scales
__device__ float g_c0[BB];            // chunk0 fwd log-scale
__device__ float g_nump[NCH][BB];     // numerator partials per chunk
__device__ int   g_len[BB];
__device__ float g_llh[BB];
__device__ int   g_tags64;

// ---- helpers ----
__device__ __forceinline__ int ldtag(const void* t, size_t i, int is64) {
    return is64 ? (int)((const long long*)t)[i] : ((const int*)t)[i];
}
__device__ __forceinline__ unsigned long long pk2(float a, float b) {
    unsigned long long r; asm("mov.b64 %0,{%1,%2};" : "=l"(r) : "f"(a), "f"(b)); return r;
}
__device__ __forceinline__ void up2(unsigned long long v, float& a, float& b) {
    asm("mov.b64 {%0,%1},%2;" : "=f"(a), "=f"(b) : "l"(v));
}
__device__ __forceinline__ unsigned long long fma2(unsigned long long a, unsigned long long b,
                                                   unsigned long long c) {
    unsigned long long d; asm("fma.rn.f32x2 %0,%1,%2,%3;" : "=l"(d) : "l"(a), "l"(b), "l"(c)); return d;
}
__device__ __forceinline__ unsigned long long mul2(unsigned long long a, unsigned long long b) {
    unsigned long long d; asm("mul.rn.f32x2 %0,%1,%2;" : "=l"(d) : "l"(a), "l"(b)); return d;
}
// bf16x2 (u32) -> packed f32x2 (u64); exact via <<16
__device__ __forceinline__ unsigned long long bfup(uint32_t w) {
    unsigned long long r;
    asm("{.reg .b32 lo,hi; shl.b32 lo,%1,16; and.b32 hi,%1,0xffff0000U; mov.b64 %0,{lo,hi};}"
        : "=l"(r) : "r"(w));
    return r;
}
__device__ __forceinline__ uint32_t cvtbf2(float lo, float hi) {
    uint32_t r; asm("cvt.rn.satfinite.bf16x2.f32 %0,%1,%2;" : "=r"(r) : "f"(hi), "f"(lo)); return r;
}

// ---- kernel 1: tags dtype detection ----
__global__ void detect_kernel(const int* __restrict__ t32) {
    int lane = threadIdx.x;                       // 32 threads
    int nz = t32[2*lane + 1] | t32[2*(lane+32) + 1];
    unsigned m = __ballot_sync(0xffffffffu, nz != 0);
    if (lane == 0) g_tags64 = (m == 0) ? 1 : 0;
}

// ---- kernel 2: per-row valid length, one WARP per row, 2 ballot rounds ----
// valid positions are a prefix; len in [1024, 2048].
__global__ __launch_bounds__(1024) void len_kernel(const void* __restrict__ tags) {
    int warp = (blockIdx.x * 1024 + threadIdx.x) >> 5;   // 0..2047 = row
    int lane = threadIdx.x & 31;
    const int is64 = g_tags64;
    size_t tb = (size_t)warp * LL;
    // round 1: probe 1024 + 32*lane; valid iff pos < len
    int p1 = 1024 + lane * 32;
    int v1 = ldtag(tags, tb + p1, is64) != 0;
    unsigned m1 = __ballot_sync(0xffffffffu, v1);
    int h = 31 - __clz(m1);                // m1==0 -> h=-1 (len==1024 case)
    int base = 1024 + 32 * h;              // len in (base, base+32]
    // round 2: probe base+1+lane
    int p2 = base + 1 + lane;
    int v2 = (p2 <= LL - 1) && (ldtag(tags, tb + p2, is64) != 0);
    unsigned m2 = __ballot_sync(0xffffffffu, v2);
    if (lane == 0) g_len[warp] = base + 1 + __popc(m2);
}

// ---- kernel 3: fused chunk pass (stage tile once; fwd+bwd+numerator) ----
__global__ __launch_bounds__(64) void crf_pass(
    const float* __restrict__ em, const float* __restrict__ trans,
    const float* __restrict__ st, const float* __restrict__ en,
    const void* __restrict__ tags)
{
    __shared__ uint32_t sW[64][132];   // bf16x2 exp(em): [row][step*4+jp]; 528B stride (16B aligned)
    __shared__ uint8_t  sTag[64][40];  // tag values (0..8) per [row][step]
    __shared__ ulonglong2 sEf[16];     // fwd: sEf[2k+h] = pack(E[k][4h..4h+3])
    __shared__ ulonglong2 sEb[16];     // bwd: sEb[2j+h] = pack(E[4h..4h+3][j])
    __shared__ float sTr[64], sSt[8], sEn[8];

    const int tx = threadIdx.x;        // 0..63
    const int ch = blockIdx.y;         // 0..63
    const int b0 = blockIdx.x << 6;    // 64 rows per block
    const int tbase = ch << 5;         // 32 steps per chunk
    const int is64 = g_tags64;

    // constants
    sTr[tx] = trans[tx];
    if (tx < 16) {
        int k = tx >> 1, h = tx & 1;
        float a0 = __expf(trans[k*8 + h*4 + 0]);
        float a1 = __expf(trans[k*8 + h*4 + 1]);
        float a2 = __expf(trans[k*8 + h*4 + 2]);
        float a3 = __expf(trans[k*8 + h*4 + 3]);
        ulonglong2 v; v.x = pk2(a0, a1); v.y = pk2(a2, a3);
        sEf[tx] = v;
    } else if (tx < 32) {
        int u = tx - 16; int j = u >> 1, h = u & 1;
        float a0 = __expf(trans[(h*4 + 0)*8 + j]);
        float a1 = __expf(trans[(h*4 + 1)*8 + j]);
        float a2 = __expf(trans[(h*4 + 2)*8 + j]);
        float a3 = __expf(trans[(h*4 + 3)*8 + j]);
        ulonglong2 v; v.x = pk2(a0, a1); v.y = pk2(a2, a3);
        sEb[u] = v;
    } else if (tx < 40) { sSt[tx - 32] = st[tx - 32]; }
    else if (tx < 48)   { sEn[tx - 40] = en[tx - 40]; }

    // ---- stage tags: [row][32 steps] -> u8, coalesced ----
    if (is64) {
        const uint4* tp = (const uint4*)tags;      // 16B = 2 i64 tags; 16 uint4 per row
        #pragma unroll
        for (int it = 0; it < 16; it++) {
            int idx = it * 64 + tx;                // 0..1023
            int row = idx >> 4, v = idx & 15;
            uint4 t = tp[(size_t)(b0 + row) * 1024 + (tbase >> 1) + v];
            sTag[row][v*2]     = (uint8_t)t.x;
            sTag[row][v*2 + 1] = (uint8_t)t.z;
        }
    } else {
        const uint4* tp = (const uint4*)tags;      // 16B = 4 i32 tags; 8 uint4 per row
        #pragma unroll
        for (int it = 0; it < 8; it++) {
            int idx = it * 64 + tx;                // 0..511
            int row = idx >> 3, v = idx & 7;
            uint4 t = tp[(size_t)(b0 + row) * 512 + (tbase >> 2) + v];
            sTag[row][v*4]     = (uint8_t)t.x;
            sTag[row][v*4 + 1] = (uint8_t)t.y;
            sTag[row][v*4 + 2] = (uint8_t)t.z;
            sTag[row][v*4 + 3] = (uint8_t)t.w;
        }
    }

    // ---- stage emissions: coalesced float4 loads, exp -> bf16x2 to SMEM ----
    {
        const float4* em4 = (const float4*)em;
        #pragma unroll 1
        for (int r8 = 0; r8 < 64; r8 += 8) {
            float4 v[8];
            #pragma unroll
            for (int k = 0; k < 8; k++)
                v[k] = em4[(size_t)(b0 + r8 + k) * 4096 + tbase * 2 + tx];
            #pragma unroll
            for (int k = 0; k < 8; k++) {
                float e0 = __expf(v[k].x), e1 = __expf(v[k].y);
                float e2 = __expf(v[k].z), e3 = __expf(v[k].w);
                uint2 w; w.x = cvtbf2(e0, e1); w.y = cvtbf2(e2, e3);
                *(uint2*)&sW[r8 + k][tx * 2] = w;
            }
        }
    }
    __syncthreads();

    // ---- compute: thread tx owns row b0+tx ----
    const int b = b0 + tx;
    const int len = g_len[b];
    int nact = len - tbase; nact = nact < 0 ? 0 : (nact > CS ? CS : nact);
    const int wmax = __reduce_max_sync(0xffffffffu, nact);

    // ================= forward =================
    {
        float p[8]; float c = 0.f, num = 0.f;
        int prev, i0;
        if (ch == 0) {
            const float* emrow = em + (size_t)b * ROWF;
            float a[8], m = -1e30f;
            #pragma unroll
            for (int j = 0; j < 8; j++) { a[j] = sSt[j] + emrow[j]; m = fmaxf(m, a[j]); }
            float S = 0.f;
            #pragma unroll
            for (int j = 0; j < 8; j++) { p[j] = __expf(a[j] - m); S += p[j]; }
            float rS = __frcp_rn(S);
            #pragma unroll
            for (int j = 0; j < 8; j++) p[j] *= rS;
            c = m + __logf(S);
            int s0 = (int)sTag[tx][0] - 1;
            num = sSt[s0] + emrow[s0];
            prev = s0; i0 = 1;
        } else {
            #pragma unroll
            for (int j = 0; j < 8; j++) p[j] = 0.125f;
            prev = ldtag(tags, (size_t)b * LL + tbase - 1, is64) - 1;
            i0 = 0;
        }
        for (int i = i0; i < wmax; i++) {
            uint4 w4 = *(const uint4*)&sW[tx][i << 2];
            if (i < nact) {
                int s1 = (int)sTag[tx][i] - 1;
                uint32_t wsel = (s1 & 4) ? ((s1 & 2) ? w4.w : w4.z)
                                         : ((s1 & 2) ? w4.y : w4.x);
                float wf = (s1 & 1) ? __uint_as_float(wsel & 0xffff0000u)
                                    : __uint_as_float(wsel << 16);
                num += sTr[(prev << 3) + s1] + __logf(wf);
                prev = s1;
                unsigned long long q01 = 0, q23 = 0, q45 = 0, q67 = 0;
                #pragma unroll
                for (int k = 0; k < 8; k++) {
                    unsigned long long pk = pk2(p[k], p[k]);
                    ulonglong2 e0 = sEf[2*k], e1 = sEf[2*k + 1];
                    q01 = fma2(pk, e0.x, q01); q23 = fma2(pk, e0.y, q23);
                    q45 = fma2(pk, e1.x, q45); q67 = fma2(pk, e1.y, q67);
                }
                q01 = mul2(q01, bfup(w4.x)); q23 = mul2(q23, bfup(w4.y));
                q45 = mul2(q45, bfup(w4.z)); q67 = mul2(q67, bfup(w4.w));
                up2(q01, p[0], p[1]); up2(q23, p[2], p[3]);
                up2(q45, p[4], p[5]); up2(q67, p[6], p[7]);
            }
            if ((i & 7) == 7) {   // deferred normalization
                float S = ((p[0]+p[1]) + (p[2]+p[3])) + ((p[4]+p[5]) + (p[6]+p[7]));
                float rS = __frcp_rn(S);
                #pragma unroll
                for (int j = 0; j < 8; j++) p[j] *= rS;
                if (ch == 0) c += __logf(S);
            }
        }
        {   // final norm (double-norm harmless: log(1)=0)
            float S = ((p[0]+p[1]) + (p[2]+p[3])) + ((p[4]+p[5]) + (p[6]+p[7]));
            float rS = __frcp_rn(S);
            #pragma unroll
            for (int j = 0; j < 8; j++) p[j] *= rS;
            if (ch == 0) { c += __logf(S); g_c0[b] = c; }
        }
        #pragma unroll
        for (int j = 0; j < 8; j++) g_v[ch][j][b] = p[j];
        g_nump[ch][b] = num;
    }

    // ================= backward =================
    if (ch > 0) {
        float r[8]; float psi = 0.f;
        if (ch == NCH - 1) {
            #pragma unroll
            for (int j = 0; j < 8; j++) r[j] = __expf(sEn[j]);
        } else {
            #pragma unroll
            for (int j = 0; j < 8; j++) r[j] = 1.0f;
        }
        for (int i = wmax - 1; i >= 0; i--) {
            uint4 w4 = *(const uint4*)&sW[tx][i << 2];
            if (i < nact) {
                unsigned long long g01 = mul2(pk2(r[0], r[1]), bfup(w4.x));
                unsigned long long g23 = mul2(pk2(r[2], r[3]), bfup(w4.y));
                unsigned long long g45 = mul2(pk2(r[4], r[5]), bfup(w4.z));
                unsigned long long g67 = mul2(pk2(r[6], r[7]), bfup(w4.w));
                float g[8];
                up2(g01, g[0], g[1]); up2(g23, g[2], g[3]);
                up2(g45, g[4], g[5]); up2(g67, g[6], g[7]);
                unsigned long long n01 = 0, n23 = 0, n45 = 0, n67 = 0;
                #pragma unroll
                for (int j = 0; j < 8; j++) {
                    unsigned long long gk = pk2(g[j], g[j]);
                    ulonglong2 e0 = sEb[2*j], e1 = sEb[2*j + 1];
                    n01 = fma2(gk, e0.x, n01); n23 = fma2(gk, e0.y, n23);
                    n45 = fma2(gk, e1.x, n45); n67 = fma2(gk, e1.y, n67);
                }
                up2(n01, r[0], r[1]); up2(n23, r[2], r[3]);
                up2(n45, r[4], r[5]); up2(n67, r[6], r[7]);
            }
            if ((i & 7) == 0 && i > 0) {
                float S = ((r[0]+r[1]) + (r[2]+r[3])) + ((r[4]+r[5]) + (r[6]+r[7]));
                float rS = __frcp_rn(S);
                #pragma unroll
                for (int j = 0; j < 8; j++) r[j] *= rS;
                psi += __logf(S);
            }
        }
        {
            float S = ((r[0]+r[1]) + (r[2]+r[3])) + ((r[4]+r[5]) + (r[6]+r[7]));
            float rS = __frcp_rn(S);
            #pragma unroll
            for (int j = 0; j < 8; j++) r[j] *= rS;
            psi += __logf(S);
        }
        #pragma unroll
        for (int j = 0; j < 8; j++) g_u[ch][j][b] = r[j];
        g_psi[ch][b] = psi;
    }
}

// ---- kernel 4: combine, fully coalesced: 32 rows/block, k split across 8 groups ----
// denom = c0 + sum_{k=1..62, k*32<len} [psi[k] + log(v[k-1].u[k])]
//            + psi[63] + log(v[k_last].u[63]),  k_last = min(62, (len-1)>>5)
__global__ __launch_bounds__(256) void combine_kernel(
    const float* __restrict__ en, const void* __restrict__ tags)
{
    __shared__ float sAcc[8][33];
    int tx = threadIdx.x;
    int bo = tx & 31, kk = tx >> 5;       // lanes vary b -> all loads coalesced
    int b = blockIdx.x * 32 + bo;
    const int len = g_len[b];

    float acc = 0.f;
    #pragma unroll
    for (int h = 0; h < 8; h++) {
        int k = kk + 8 * h;               // this thread's 8 chunk indices
        acc += g_nump[k][b];
        if (k >= 1 && k <= NCH - 2 && k * CS < len) {
            float dot = 0.f;
            #pragma unroll
            for (int j = 0; j < 8; j++) dot += g_v[k - 1][j][b] * g_u[k][j][b];
            acc -= g_psi[k][b] + __logf(dot);   // denom enters negatively
        }
    }
    if (kk == 0) {
        const int is64 = g_tags64;
        int sl = ldtag(tags, (size_t)b * LL + len - 1, is64) - 1;
        int k_last = (len - 1) >> 5; if (k_last > NCH - 2) k_last = NCH - 2;
        float dot = 0.f;
        #pragma unroll
        for (int j = 0; j < 8; j++) dot += g_v[k_last][j][b] * g_u[NCH - 1][j][b];
        acc += en[sl] - g_c0[b] - (g_psi[NCH - 1][b] + __logf(dot));
    }
    sAcc[kk][bo] = acc;
    __syncthreads();
    if (tx < 32) {
        float s = 0.f;
        #pragma unroll
        for (int q = 0; q < 8; q++) s += sAcc[q][tx];
        g_llh[blockIdx.x * 32 + tx] = s;  // = num - denom
    }
}

// ---- kernel 5: mean reduce ----
__global__ void reduce_kernel(float* __restrict__ out) {
    __shared__ float sw[32];
    int tx = threadIdx.x;                          // 1024 threads
    float s = g_llh[tx] + g_llh[tx + 1024];
    #pragma unroll
    for (int o = 16; o > 0; o >>= 1) s += __shfl_xor_sync(0xffffffffu, s, o);
    if ((tx & 31) == 0) sw[tx >> 5] = s;
    __syncthreads();
    if (tx < 32) {
        float v = sw[tx];
        #pragma unroll
        for (int o = 16; o > 0; o >>= 1) v += __shfl_xor_sync(0xffffffffu, v, o);
        if (tx == 0) out[0] = -v / (float)BB;
    }
}

extern "C" void kernel_launch(void* const* d_in, const int* in_sizes, int n_in,
                              void* d_out, int out_size) {
    const float* em    = (const float*)d_in[0];
    const float* trans = (const float*)d_in[1];
    const float* st    = (const float*)d_in[2];
    const float* en    = (const float*)d_in[3];
    const void*  tags  = d_in[4];
    (void)in_sizes; (void)n_in; (void)out_size;

    detect_kernel<<<1, 32>>>((const int*)tags);
    len_kernel<<<BB / 32, 1024>>>(tags);
    crf_pass<<<dim3(32, 64), 64>>>(em, trans, st, en, tags);
    combine_kernel<<<BB / 32, 256>>>(en, tags);
    reduce_kernel<<<1, 1024>>>((float*)d_out);
}

// round 16
// speedup vs baseline: 3.0813x; 1.2501x over previous
#include <cuda_runtime.h>
#include <cstdint>

#define BB 2048
#define LL 2048
#define ROWF 16384          // LL*8 floats per emissions row
#define CS 32               // steps per chunk
#define NCH 64              // chunks per row

// ---- scratch (__device__ globals; allocation-free rule) ----
__device__ float g_v[NCH][8][BB];     // fwd directions per chunk
__device__ float g_u[NCH][8][BB];     // bwd vectors per chunk (u[0] unused)
__device__ float g_psi[NCH][BB];      // bwd log-scales
__device__ float g_c0[BB];            // chunk0 fwd log-scale
__device__ float g_nump[NCH][BB];     // numerator partials per chunk
__device__ float g_part[2][BB];       // combine partials (k-halves)
__device__ int   g_len[BB];
__device__ int   g_tags64;

// ---- helpers ----
__device__ __forceinline__ int ldtag(const void* t, size_t i, int is64) {
    return is64 ? (int)((const long long*)t)[i] : ((const int*)t)[i];
}
__device__ __forceinline__ unsigned long long pk2(float a, float b) {
    unsigned long long r; asm("mov.b64 %0,{%1,%2};" : "=l"(r) : "f"(a), "f"(b)); return r;
}
__device__ __forceinline__ void up2(unsigned long long v, float& a, float& b) {
    asm("mov.b64 {%0,%1},%2;" : "=f"(a), "=f"(b) : "l"(v));
}
__device__ __forceinline__ unsigned long long fma2(unsigned long long a, unsigned long long b,
                                                   unsigned long long c) {
    unsigned long long d; asm("fma.rn.f32x2 %0,%1,%2,%3;" : "=l"(d) : "l"(a), "l"(b), "l"(c)); return d;
}
__device__ __forceinline__ unsigned long long mul2(unsigned long long a, unsigned long long b) {
    unsigned long long d; asm("mul.rn.f32x2 %0,%1,%2;" : "=l"(d) : "l"(a), "l"(b)); return d;
}
// bf16x2 (u32) -> packed f32x2 (u64); exact via <<16
__device__ __forceinline__ unsigned long long bfup(uint32_t w) {
    unsigned long long r;
    asm("{.reg .b32 lo,hi; shl.b32 lo,%1,16; and.b32 hi,%1,0xffff0000U; mov.b64 %0,{lo,hi};}"
        : "=l"(r) : "r"(w));
    return r;
}
__device__ __forceinline__ uint32_t cvtbf2(float lo, float hi) {
    uint32_t r; asm("cvt.rn.satfinite.bf16x2.f32 %0,%1,%2;" : "=r"(r) : "f"(hi), "f"(lo)); return r;
}

// ---- kernel 1: tags dtype detection ----
__global__ void detect_kernel(const int* __restrict__ t32) {
    int lane = threadIdx.x;                       // 32 threads
    int nz = t32[2*lane + 1] | t32[2*(lane+32) + 1];
    unsigned m = __ballot_sync(0xffffffffu, nz != 0);
    if (lane == 0) g_tags64 = (m == 0) ? 1 : 0;
}

// ---- kernel 2: per-row valid length, one WARP per row, 2 ballot rounds ----
__global__ __launch_bounds__(1024) void len_kernel(const void* __restrict__ tags) {
    int warp = (blockIdx.x * 1024 + threadIdx.x) >> 5;   // 0..2047 = row
    int lane = threadIdx.x & 31;
    const int is64 = g_tags64;
    size_t tb = (size_t)warp * LL;
    int p1 = 1024 + lane * 32;
    int v1 = ldtag(tags, tb + p1, is64) != 0;
    unsigned m1 = __ballot_sync(0xffffffffu, v1);
    int h = 31 - __clz(m1);                // m1==0 -> h=-1 (len==1024 case)
    int base = 1024 + 32 * h;
    int p2 = base + 1 + lane;
    int v2 = (p2 <= LL - 1) && (ldtag(tags, tb + p2, is64) != 0);
    unsigned m2 = __ballot_sync(0xffffffffu, v2);
    if (lane == 0) g_len[warp] = base + 1 + __popc(m2);
}

// ---- kernel 3: fused chunk pass; fwd and bwd run CONCURRENTLY on thread halves ----
__global__ __launch_bounds__(128) void crf_pass(
    const float* __restrict__ em, const float* __restrict__ trans,
    const float* __restrict__ st, const float* __restrict__ en,
    const void* __restrict__ tags)
{
    __shared__ uint32_t sW[64][132];   // bf16x2 exp(em): [row][step*4+jp]
    __shared__ uint8_t  sTag[64][40];
    __shared__ ulonglong2 sEf[16];     // fwd: sEf[2k+h] = pack(E[k][4h..4h+3])
    __shared__ ulonglong2 sEb[16];     // bwd: sEb[2j+h] = pack(E[4h..4h+3][j])
    __shared__ float sTr[64], sSt[8], sEn[8];

    const int tx = threadIdx.x;        // 0..127
    const int ch = blockIdx.y;         // 0..63
    const int b0 = blockIdx.x << 6;    // 64 rows per block
    const int tbase = ch << 5;         // 32 steps per chunk
    const int is64 = g_tags64;

    // constants
    if (tx < 64) sTr[tx] = trans[tx];
    if (tx < 16) {
        int k = tx >> 1, h = tx & 1;
        float a0 = __expf(trans[k*8 + h*4 + 0]);
        float a1 = __expf(trans[k*8 + h*4 + 1]);
        float a2 = __expf(trans[k*8 + h*4 + 2]);
        float a3 = __expf(trans[k*8 + h*4 + 3]);
        ulonglong2 v; v.x = pk2(a0, a1); v.y = pk2(a2, a3);
        sEf[tx] = v;
    } else if (tx < 32) {
        int u = tx - 16; int j = u >> 1, h = u & 1;
        float a0 = __expf(trans[(h*4 + 0)*8 + j]);
        float a1 = __expf(trans[(h*4 + 1)*8 + j]);
        float a2 = __expf(trans[(h*4 + 2)*8 + j]);
        float a3 = __expf(trans[(h*4 + 3)*8 + j]);
        ulonglong2 v; v.x = pk2(a0, a1); v.y = pk2(a2, a3);
        sEb[u] = v;
    } else if (tx < 40) { sSt[tx - 32] = st[tx - 32]; }
    else if (tx < 48)   { sEn[tx - 40] = en[tx - 40]; }

    // ---- stage tags (coalesced) ----
    if (is64) {
        const uint4* tp = (const uint4*)tags;      // 16 uint4 per row
        #pragma unroll
        for (int it = 0; it < 8; it++) {
            int idx = it * 128 + tx;               // 0..1023
            int row = idx >> 4, v = idx & 15;
            uint4 t = tp[(size_t)(b0 + row) * 1024 + (tbase >> 1) + v];
            sTag[row][v*2]     = (uint8_t)t.x;
            sTag[row][v*2 + 1] = (uint8_t)t.z;
        }
    } else {
        const uint4* tp = (const uint4*)tags;      // 8 uint4 per row
        #pragma unroll
        for (int it = 0; it < 4; it++) {
            int idx = it * 128 + tx;               // 0..511
            int row = idx >> 3, v = idx & 7;
            uint4 t = tp[(size_t)(b0 + row) * 512 + (tbase >> 2) + v];
            sTag[row][v*4]     = (uint8_t)t.x;
            sTag[row][v*4 + 1] = (uint8_t)t.y;
            sTag[row][v*4 + 2] = (uint8_t)t.z;
            sTag[row][v*4 + 3] = (uint8_t)t.w;
        }
    }

    // ---- stage emissions: coalesced float4, exp -> bf16x2 ----
    {
        const float4* em4 = (const float4*)em;
        #pragma unroll 4
        for (int it = 0; it < 32; it++) {
            int idx = it * 128 + tx;               // 0..4095
            int row = idx >> 6, col = idx & 63;
            float4 v = em4[(size_t)(b0 + row) * 4096 + tbase * 2 + col];
            uint2 w;
            w.x = cvtbf2(__expf(v.x), __expf(v.y));
            w.y = cvtbf2(__expf(v.z), __expf(v.w));
            *(uint2*)&sW[row][col * 2] = w;
        }
    }
    __syncthreads();

    // ---- compute: tx<64 forward for row tx; tx>=64 backward for row tx-64 ----
    const int row = tx & 63;
    const int b = b0 + row;
    const int len = g_len[b];
    int nact = len - tbase; nact = nact < 0 ? 0 : (nact > CS ? CS : nact);
    const int wmax = __reduce_max_sync(0xffffffffu, nact);   // per-warp; fwd/bwd warp pairs match

    if (tx < 64) {
        // ================= forward =================
        float p[8]; float c = 0.f, num = 0.f;
        int prev, i0;
        if (ch == 0) {
            const float* emrow = em + (size_t)b * ROWF;
            float a[8], m = -1e30f;
            #pragma unroll
            for (int j = 0; j < 8; j++) { a[j] = sSt[j] + emrow[j]; m = fmaxf(m, a[j]); }
            float S = 0.f;
            #pragma unroll
            for (int j = 0; j < 8; j++) { p[j] = __expf(a[j] - m); S += p[j]; }
            float rS = __frcp_rn(S);
            #pragma unroll
            for (int j = 0; j < 8; j++) p[j] *= rS;
            c = m + __logf(S);
            int s0 = (int)sTag[row][0] - 1;
            num = sSt[s0] + emrow[s0];
            prev = s0; i0 = 1;
        } else {
            #pragma unroll
            for (int j = 0; j < 8; j++) p[j] = 0.125f;
            prev = ldtag(tags, (size_t)b * LL + tbase - 1, is64) - 1;
            i0 = 0;
        }
        for (int i = i0; i < wmax; i++) {
            uint4 w4 = *(const uint4*)&sW[row][i << 2];
            if (i < nact) {
                int s1 = (int)sTag[row][i] - 1;
                uint32_t wsel = (s1 & 4) ? ((s1 & 2) ? w4.w : w4.z)
                                         : ((s1 & 2) ? w4.y : w4.x);
                float wf = (s1 & 1) ? __uint_as_float(wsel & 0xffff0000u)
                                    : __uint_as_float(wsel << 16);
                num += sTr[(prev << 3) + s1] + __logf(wf);
                prev = s1;
                unsigned long long q01 = 0, q23 = 0, q45 = 0, q67 = 0;
                #pragma unroll
                for (int k = 0; k < 8; k++) {
                    unsigned long long pk = pk2(p[k], p[k]);
                    ulonglong2 e0 = sEf[2*k], e1 = sEf[2*k + 1];
                    q01 = fma2(pk, e0.x, q01); q23 = fma2(pk, e0.y, q23);
                    q45 = fma2(pk, e1.x, q45); q67 = fma2(pk, e1.y, q67);
                }
                q01 = mul2(q01, bfup(w4.x)); q23 = mul2(q23, bfup(w4.y));
                q45 = mul2(q45, bfup(w4.z)); q67 = mul2(q67, bfup(w4.w));
                up2(q01, p[0], p[1]); up2(q23, p[2], p[3]);
                up2(q45, p[4], p[5]); up2(q67, p[6], p[7]);
            }
            if ((i & 7) == 7) {   // deferred normalization
                float S = ((p[0]+p[1]) + (p[2]+p[3])) + ((p[4]+p[5]) + (p[6]+p[7]));
                float rS = __frcp_rn(S);
                #pragma unroll
                for (int j = 0; j < 8; j++) p[j] *= rS;
                if (ch == 0) c += __logf(S);
            }
        }
        {
            float S = ((p[0]+p[1]) + (p[2]+p[3])) + ((p[4]+p[5]) + (p[6]+p[7]));
            float rS = __frcp_rn(S);
            #pragma unroll
            for (int j = 0; j < 8; j++) p[j] *= rS;
            if (ch == 0) { c += __logf(S); g_c0[b] = c; }
        }
        #pragma unroll
        for (int j = 0; j < 8; j++) g_v[ch][j][b] = p[j];
        g_nump[ch][b] = num;
    } else if (ch > 0) {
        // ================= backward =================
        float r[8]; float psi = 0.f;
        if (ch == NCH - 1) {
            #pragma unroll
            for (int j = 0; j < 8; j++) r[j] = __expf(sEn[j]);
        } else {
            #pragma unroll
            for (int j = 0; j < 8; j++) r[j] = 1.0f;
        }
        for (int i = wmax - 1; i >= 0; i--) {
            uint4 w4 = *(const uint4*)&sW[row][i << 2];
            if (i < nact) {
                unsigned long long g01 = mul2(pk2(r[0], r[1]), bfup(w4.x));
                unsigned long long g23 = mul2(pk2(r[2], r[3]), bfup(w4.y));
                unsigned long long g45 = mul2(pk2(r[4], r[5]), bfup(w4.z));
                unsigned long long g67 = mul2(pk2(r[6], r[7]), bfup(w4.w));
                float g[8];
                up2(g01, g[0], g[1]); up2(g23, g[2], g[3]);
                up2(g45, g[4], g[5]); up2(g67, g[6], g[7]);
                unsigned long long n01 = 0, n23 = 0, n45 = 0, n67 = 0;
                #pragma unroll
                for (int j = 0; j < 8; j++) {
                    unsigned long long gk = pk2(g[j], g[j]);
                    ulonglong2 e0 = sEb[2*j], e1 = sEb[2*j + 1];
                    n01 = fma2(gk, e0.x, n01); n23 = fma2(gk, e0.y, n23);
                    n45 = fma2(gk, e1.x, n45); n67 = fma2(gk, e1.y, n67);
                }
                up2(n01, r[0], r[1]); up2(n23, r[2], r[3]);
                up2(n45, r[4], r[5]); up2(n67, r[6], r[7]);
            }
            if ((i & 7) == 0 && i > 0) {
                float S = ((r[0]+r[1]) + (r[2]+r[3])) + ((r[4]+r[5]) + (r[6]+r[7]));
                float rS = __frcp_rn(S);
                #pragma unroll
                for (int j = 0; j < 8; j++) r[j] *= rS;
                psi += __logf(S);
            }
        }
        {
            float S = ((r[0]+r[1]) + (r[2]+r[3])) + ((r[4]+r[5]) + (r[6]+r[7]));
            float rS = __frcp_rn(S);
            #pragma unroll
            for (int j = 0; j < 8; j++) r[j] *= rS;
            psi += __logf(S);
        }
        #pragma unroll
        for (int j = 0; j < 8; j++) g_u[ch][j][b] = r[j];
        g_psi[ch][b] = psi;
    }
}

// ---- kernel 4: combine, thread per (k,b) term; 1024-thr blocks (32k x 32b) ----
// grid = (64 b-tiles, 2 k-tiles); partials to g_part[kt][b]
__global__ __launch_bounds__(1024) void combine_kernel(
    const float* __restrict__ en, const void* __restrict__ tags)
{
    __shared__ float sAcc[32][33];
    int tx = threadIdx.x;
    int bo = tx & 31, kk = tx >> 5;       // lanes vary b -> coalesced
    int kt = blockIdx.y;
    int k  = kt * 32 + kk;
    int b  = blockIdx.x * 32 + bo;
    const int len = g_len[b];

    float acc = g_nump[k][b];
    if (k >= 1 && k <= NCH - 2 && k * CS < len) {
        float dot = 0.f;
        #pragma unroll
        for (int j = 0; j < 8; j++) dot += g_v[k - 1][j][b] * g_u[k][j][b];
        acc -= g_psi[k][b] + __logf(dot);     // denom enters negatively
    }
    if (k == NCH - 1) {                       // final chunk exact term + c0 + end
        const int is64 = g_tags64;
        int sl = ldtag(tags, (size_t)b * LL + len - 1, is64) - 1;
        int k_last = (len - 1) >> 5; if (k_last > NCH - 2) k_last = NCH - 2;
        float dot = 0.f;
        #pragma unroll
        for (int j = 0; j < 8; j++) dot += g_v[k_last][j][b] * g_u[NCH - 1][j][b];
        acc += en[sl] - g_c0[b] - (g_psi[NCH - 1][b] + __logf(dot));
    }
    sAcc[kk][bo] = acc;
    __syncthreads();
    if (tx < 32) {
        float s = 0.f;
        #pragma unroll
        for (int q = 0; q < 32; q++) s += sAcc[q][tx];
        g_part[kt][blockIdx.x * 32 + tx] = s;
    }
}

// ---- kernel 5: mean reduce ----
__global__ void reduce_kernel(float* __restrict__ out) {
    __shared__ float sw[32];
    int tx = threadIdx.x;                          // 1024 threads
    float s = (g_part[0][tx] + g_part[1][tx])
            + (g_part[0][tx + 1024] + g_part[1][tx + 1024]);
    #pragma unroll
    for (int o = 16; o > 0; o >>= 1) s += __shfl_xor_sync(0xffffffffu, s, o);
    if ((tx & 31) == 0) sw[tx >> 5] = s;
    __syncthreads();
    if (tx < 32) {
        float v = sw[tx];
        #pragma unroll
        for (int o = 16; o > 0; o >>= 1) v += __shfl_xor_sync(0xffffffffu, v, o);
        if (tx == 0) out[0] = -v / (float)BB;
    }
}

extern "C" void kernel_launch(void* const* d_in, const int* in_sizes, int n_in,
                              void* d_out, int out_size) {
    const float* em    = (const float*)d_in[0];
    const float* trans = (const float*)d_in[1];
    const float* st    = (const float*)d_in[2];
    const float* en    = (const float*)d_in[3];
    const void*  tags  = d_in[4];
    (void)in_sizes; (void)n_in; (void)out_size;

    detect_kernel<<<1, 32>>>((const int*)tags);
    len_kernel<<<BB / 32, 1024>>>(tags);
    crf_pass<<<dim3(32, 64), 128>>>(em, trans, st, en, tags);
    combine_kernel<<<dim3(BB / 32, 2), 1024>>>(en, tags);
    reduce_kernel<<<1, 1024>>>((float*)d_out);
}

// round 17
// speedup vs baseline: 3.2770x; 1.0635x over previous
#include <cuda_runtime.h>
#include <cstdint>

#define BB 2048
#define LL 2048
#define ROWF 16384          // LL*8 floats per emissions row
#define CS 32               // steps per chunk
#define NCH 64              // chunks per row

// ---- scratch (__device__ globals; allocation-free rule) ----
__device__ float g_v[NCH][8][BB];     // fwd directions per chunk
__device__ float g_u[NCH][8][BB];     // bwd vectors per chunk (u[0] unused)
__device__ float g_psi[NCH][BB];      // bwd log-scales
__device__ float g_c0[BB];            // chunk0 fwd log-scale
__device__ float g_nump[NCH][BB];     // numerator partials per chunk
__device__ int   g_len[BB];
__device__ double g_acc;              // fused-reduce accumulator (starts 0; reset each replay)
__device__ unsigned g_cnt;            // completion ticket (starts 0; reset each replay)

// ---- helpers ----
__device__ __forceinline__ int ldtag(const void* t, size_t i, int is64) {
    return is64 ? (int)((const long long*)t)[i] : ((const int*)t)[i];
}
__device__ __forceinline__ unsigned long long pk2(float a, float b) {
    unsigned long long r; asm("mov.b64 %0,{%1,%2};" : "=l"(r) : "f"(a), "f"(b)); return r;
}
__device__ __forceinline__ void up2(unsigned long long v, float& a, float& b) {
    asm("mov.b64 {%0,%1},%2;" : "=f"(a), "=f"(b) : "l"(v));
}
__device__ __forceinline__ unsigned long long fma2(unsigned long long a, unsigned long long b,
                                                   unsigned long long c) {
    unsigned long long d; asm("fma.rn.f32x2 %0,%1,%2,%3;" : "=l"(d) : "l"(a), "l"(b), "l"(c)); return d;
}
__device__ __forceinline__ unsigned long long mul2(unsigned long long a, unsigned long long b) {
    unsigned long long d; asm("mul.rn.f32x2 %0,%1,%2;" : "=l"(d) : "l"(a), "l"(b)); return d;
}
// bf16x2 (u32) -> packed f32x2 (u64); exact via <<16
__device__ __forceinline__ unsigned long long bfup(uint32_t w) {
    unsigned long long r;
    asm("{.reg .b32 lo,hi; shl.b32 lo,%1,16; and.b32 hi,%1,0xffff0000U; mov.b64 %0,{lo,hi};}"
        : "=l"(r) : "r"(w));
    return r;
}
__device__ __forceinline__ uint32_t cvtbf2(float lo, float hi) {
    uint32_t r; asm("cvt.rn.satfinite.bf16x2.f32 %0,%1,%2;" : "=r"(r) : "f"(hi), "f"(lo)); return r;
}

// ---- kernel 1: per-row valid length, one WARP per row, 2 ballot rounds ----
// valid = prefix; len in [1024, 2048]. dtype detected inline: int64 tags => high
// word of tags[0] is 0; int32 => it's tags[1] in 1..8 (pos 1 valid since len>=1024).
__global__ __launch_bounds__(1024) void len_kernel(const void* __restrict__ tags) {
    const int is64 = (((const int*)tags)[1] == 0);
    int warp = (blockIdx.x * 1024 + threadIdx.x) >> 5;   // 0..2047 = row
    int lane = threadIdx.x & 31;
    size_t tb = (size_t)warp * LL;
    int p1 = 1024 + lane * 32;
    int v1 = ldtag(tags, tb + p1, is64) != 0;
    unsigned m1 = __ballot_sync(0xffffffffu, v1);
    int h = 31 - __clz(m1);                // m1==0 -> h=-1 (len==1024 case)
    int base = 1024 + 32 * h;
    int p2 = base + 1 + lane;
    int v2 = (p2 <= LL - 1) && (ldtag(tags, tb + p2, is64) != 0);
    unsigned m2 = __ballot_sync(0xffffffffu, v2);
    if (lane == 0) g_len[warp] = base + 1 + __popc(m2);
}

// ---- kernel 2: fused chunk pass; fwd and bwd run CONCURRENTLY on thread halves ----
__global__ __launch_bounds__(128) void crf_pass(
    const float* __restrict__ em, const float* __restrict__ trans,
    const float* __restrict__ st, const float* __restrict__ en,
    const void* __restrict__ tags)
{
    __shared__ uint32_t sW[64][132];   // bf16x2 exp(em): [row][step*4+jp]
    __shared__ uint8_t  sTag[64][40];
    __shared__ ulonglong2 sEf[16];     // fwd: sEf[2k+h] = pack(E[k][4h..4h+3])
    __shared__ ulonglong2 sEb[16];     // bwd: sEb[2j+h] = pack(E[4h..4h+3][j])
    __shared__ float sTr[64], sSt[8], sEn[8];

    const int tx = threadIdx.x;        // 0..127
    const int ch = blockIdx.y;         // 0..63
    const int b0 = blockIdx.x << 6;    // 64 rows per block
    const int tbase = ch << 5;         // 32 steps per chunk
    const int is64 = (((const int*)tags)[1] == 0);

    // constants
    if (tx < 64) sTr[tx] = trans[tx];
    if (tx < 16) {
        int k = tx >> 1, h = tx & 1;
        float a0 = __expf(trans[k*8 + h*4 + 0]);
        float a1 = __expf(trans[k*8 + h*4 + 1]);
        float a2 = __expf(trans[k*8 + h*4 + 2]);
        float a3 = __expf(trans[k*8 + h*4 + 3]);
        ulonglong2 v; v.x = pk2(a0, a1); v.y = pk2(a2, a3);
        sEf[tx] = v;
    } else if (tx < 32) {
        int u = tx - 16; int j = u >> 1, h = u & 1;
        float a0 = __expf(trans[(h*4 + 0)*8 + j]);
        float a1 = __expf(trans[(h*4 + 1)*8 + j]);
        float a2 = __expf(trans[(h*4 + 2)*8 + j]);
        float a3 = __expf(trans[(h*4 + 3)*8 + j]);
        ulonglong2 v; v.x = pk2(a0, a1); v.y = pk2(a2, a3);
        sEb[u] = v;
    } else if (tx < 40) { sSt[tx - 32] = st[tx - 32]; }
    else if (tx < 48)   { sEn[tx - 40] = en[tx - 40]; }

    // ---- stage tags (coalesced) ----
    if (is64) {
        const uint4* tp = (const uint4*)tags;      // 16 uint4 per row
        #pragma unroll
        for (int it = 0; it < 8; it++) {
            int idx = it * 128 + tx;               // 0..1023
            int row = idx >> 4, v = idx & 15;
            uint4 t = tp[(size_t)(b0 + row) * 1024 + (tbase >> 1) + v];
            sTag[row][v*2]     = (uint8_t)t.x;
            sTag[row][v*2 + 1] = (uint8_t)t.z;
        }
    } else {
        const uint4* tp = (const uint4*)tags;      // 8 uint4 per row
        #pragma unroll
        for (int it = 0; it < 4; it++) {
            int idx = it * 128 + tx;               // 0..511
            int row = idx >> 3, v = idx & 7;
            uint4 t = tp[(size_t)(b0 + row) * 512 + (tbase >> 2) + v];
            sTag[row][v*4]     = (uint8_t)t.x;
            sTag[row][v*4 + 1] = (uint8_t)t.y;
            sTag[row][v*4 + 2] = (uint8_t)t.z;
            sTag[row][v*4 + 3] = (uint8_t)t.w;
        }
    }

    // ---- stage emissions: coalesced float4, exp -> bf16x2 ----
    {
        const float4* em4 = (const float4*)em;
        #pragma unroll 8
        for (int it = 0; it < 32; it++) {
            int idx = it * 128 + tx;               // 0..4095
            int row = idx >> 6, col = idx & 63;
            float4 v = em4[(size_t)(b0 + row) * 4096 + tbase * 2 + col];
            uint2 w;
            w.x = cvtbf2(__expf(v.x), __expf(v.y));
            w.y = cvtbf2(__expf(v.z), __expf(v.w));
            *(uint2*)&sW[row][col * 2] = w;
        }
    }
    __syncthreads();

    // ---- compute: tx<64 forward for row tx; tx>=64 backward for row tx-64 ----
    const int row = tx & 63;
    const int b = b0 + row;
    const int len = g_len[b];
    int nact = len - tbase; nact = nact < 0 ? 0 : (nact > CS ? CS : nact);
    const int wmax = __reduce_max_sync(0xffffffffu, nact);   // per-warp; fwd/bwd warp pairs match

    if (tx < 64) {
        // ================= forward =================
        float p[8]; float c = 0.f, num = 0.f;
        int prev, i0;
        if (ch == 0) {
            const float* emrow = em + (size_t)b * ROWF;
            float a[8], m = -1e30f;
            #pragma unroll
            for (int j = 0; j < 8; j++) { a[j] = sSt[j] + emrow[j]; m = fmaxf(m, a[j]); }
            float S = 0.f;
            #pragma unroll
            for (int j = 0; j < 8; j++) { p[j] = __expf(a[j] - m); S += p[j]; }
            float rS = __frcp_rn(S);
            #pragma unroll
            for (int j = 0; j < 8; j++) p[j] *= rS;
            c = m + __logf(S);
            int s0 = (int)sTag[row][0] - 1;
            num = sSt[s0] + emrow[s0];
            prev = s0; i0 = 1;
        } else {
            #pragma unroll
            for (int j = 0; j < 8; j++) p[j] = 0.125f;
            prev = ldtag(tags, (size_t)b * LL + tbase - 1, is64) - 1;
            i0 = 0;
        }
        for (int i = i0; i < wmax; i++) {
            uint4 w4 = *(const uint4*)&sW[row][i << 2];
            if (i < nact) {
                int s1 = (int)sTag[row][i] - 1;
                uint32_t wsel = (s1 & 4) ? ((s1 & 2) ? w4.w : w4.z)
                                         : ((s1 & 2) ? w4.y : w4.x);
                float wf = (s1 & 1) ? __uint_as_float(wsel & 0xffff0000u)
                                    : __uint_as_float(wsel << 16);
                num += sTr[(prev << 3) + s1] + __logf(wf);
                prev = s1;
                unsigned long long q01 = 0, q23 = 0, q45 = 0, q67 = 0;
                #pragma unroll
                for (int k = 0; k < 8; k++) {
                    unsigned long long pk = pk2(p[k], p[k]);
                    ulonglong2 e0 = sEf[2*k], e1 = sEf[2*k + 1];
                    q01 = fma2(pk, e0.x, q01); q23 = fma2(pk, e0.y, q23);
                    q45 = fma2(pk, e1.x, q45); q67 = fma2(pk, e1.y, q67);
                }
                q01 = mul2(q01, bfup(w4.x)); q23 = mul2(q23, bfup(w4.y));
                q45 = mul2(q45, bfup(w4.z)); q67 = mul2(q67, bfup(w4.w));
                up2(q01, p[0], p[1]); up2(q23, p[2], p[3]);
                up2(q45, p[4], p[5]); up2(q67, p[6], p[7]);
            }
            if ((i & 7) == 7) {   // deferred normalization
                float S = ((p[0]+p[1]) + (p[2]+p[3])) + ((p[4]+p[5]) + (p[6]+p[7]));
                float rS = __frcp_rn(S);
                #pragma unroll
                for (int j = 0; j < 8; j++) p[j] *= rS;
                if (ch == 0) c += __logf(S);
            }
        }
        {
            float S = ((p[0]+p[1]) + (p[2]+p[3])) + ((p[4]+p[5]) + (p[6]+p[7]));
            float rS = __frcp_rn(S);
            #pragma unroll
            for (int j = 0; j < 8; j++) p[j] *= rS;
            if (ch == 0) { c += __logf(S); g_c0[b] = c; }
        }
        #pragma unroll
        for (int j = 0; j < 8; j++) g_v[ch][j][b] = p[j];
        g_nump[ch][b] = num;
    } else if (ch > 0) {
        // ================= backward =================
        float r[8]; float psi = 0.f;
        if (ch == NCH - 1) {
            #pragma unroll
            for (int j = 0; j < 8; j++) r[j] = __expf(sEn[j]);
        } else {
            #pragma unroll
            for (int j = 0; j < 8; j++) r[j] = 1.0f;
        }
        for (int i = wmax - 1; i >= 0; i--) {
            uint4 w4 = *(const uint4*)&sW[row][i << 2];
            if (i < nact) {
                unsigned long long g01 = mul2(pk2(r[0], r[1]), bfup(w4.x));
                unsigned long long g23 = mul2(pk2(r[2], r[3]), bfup(w4.y));
                unsigned long long g45 = mul2(pk2(r[4], r[5]), bfup(w4.z));
                unsigned long long g67 = mul2(pk2(r[6], r[7]), bfup(w4.w));
                float g[8];
                up2(g01, g[0], g[1]); up2(g23, g[2], g[3]);
                up2(g45, g[4], g[5]); up2(g67, g[6], g[7]);
                unsigned long long n01 = 0, n23 = 0, n45 = 0, n67 = 0;
                #pragma unroll
                for (int j = 0; j < 8; j++) {
                    unsigned long long gk = pk2(g[j], g[j]);
                    ulonglong2 e0 = sEb[2*j], e1 = sEb[2*j + 1];
                    n01 = fma2(gk, e0.x, n01); n23 = fma2(gk, e0.y, n23);
                    n45 = fma2(gk, e1.x, n45); n67 = fma2(gk, e1.y, n67);
                }
                up2(n01, r[0], r[1]); up2(n23, r[2], r[3]);
                up2(n45, r[4], r[5]); up2(n67, r[6], r[7]);
            }
            if ((i & 7) == 0 && i > 0) {
                float S = ((r[0]+r[1]) + (r[2]+r[3])) + ((r[4]+r[5]) + (r[6]+r[7]));
                float rS = __frcp_rn(S);
                #pragma unroll
                for (int j = 0; j < 8; j++) r[j] *= rS;
                psi += __logf(S);
            }
        }
        {
            float S = ((r[0]+r[1]) + (r[2]+r[3])) + ((r[4]+r[5]) + (r[6]+r[7]));
            float rS = __frcp_rn(S);
            #pragma unroll
            for (int j = 0; j < 8; j++) r[j] *= rS;
            psi += __logf(S);
        }
        #pragma unroll
        for (int j = 0; j < 8; j++) g_u[ch][j][b] = r[j];
        g_psi[ch][b] = psi;
    }
}

// ---- kernel 3: combine + fused mean-reduce (last block writes d_out) ----
// Sum over ALL (k,b) terms directly; per-row llh never materialized.
__global__ __launch_bounds__(1024) void combine_kernel(
    const float* __restrict__ en, const void* __restrict__ tags,
    float* __restrict__ out)
{
    __shared__ float sRed[32];
    int tx = threadIdx.x;
    int bo = tx & 31, kk = tx >> 5;       // lanes vary b -> coalesced
    int kt = blockIdx.y;
    int k  = kt * 32 + kk;
    int b  = blockIdx.x * 32 + bo;
    const int len = g_len[b];

    float acc = g_nump[k][b];
    if (k >= 1 && k <= NCH - 2 && k * CS < len) {
        float dot = 0.f;
        #pragma unroll
        for (int j = 0; j < 8; j++) dot += g_v[k - 1][j][b] * g_u[k][j][b];
        acc -= g_psi[k][b] + __logf(dot);     // denom enters negatively
    }
    if (k == NCH - 1) {                       // final chunk exact term + c0 + end
        const int is64 = (((const int*)tags)[1] == 0);
        int sl = ldtag(tags, (size_t)b * LL + len - 1, is64) - 1;
        int k_last = (len - 1) >> 5; if (k_last > NCH - 2) k_last = NCH - 2;
        float dot = 0.f;
        #pragma unroll
        for (int j = 0; j < 8; j++) dot += g_v[k_last][j][b] * g_u[NCH - 1][j][b];
        acc += en[sl] - g_c0[b] - (g_psi[NCH - 1][b] + __logf(dot));
    }

    // block reduction (1024 -> 1)
    #pragma unroll
    for (int o = 16; o > 0; o >>= 1) acc += __shfl_xor_sync(0xffffffffu, acc, o);
    if ((tx & 31) == 0) sRed[tx >> 5] = acc;
    __syncthreads();
    if (tx < 32) {
        float v = sRed[tx];
        #pragma unroll
        for (int o = 16; o > 0; o >>= 1) v += __shfl_xor_sync(0xffffffffu, v, o);
        if (tx == 0) {
            atomicAdd(&g_acc, (double)v);
            __threadfence();
            unsigned ticket = atomicAdd(&g_cnt, 1u);
            if (ticket == gridDim.x * gridDim.y - 1) {   // last block finalizes
                double total = g_acc;
                out[0] = (float)(-total / (double)BB);
                g_acc = 0.0;                             // reset for next graph replay
                g_cnt = 0u;
            }
        }
    }
}

extern "C" void kernel_launch(void* const* d_in, const int* in_sizes, int n_in,
                              void* d_out, int out_size) {
    const float* em    = (const float*)d_in[0];
    const float* trans = (const float*)d_in[1];
    const float* st    = (const float*)d_in[2];
    const float* en    = (const float*)d_in[3];
    const void*  tags  = d_in[4];
    (void)in_sizes; (void)n_in; (void)out_size;

    len_kernel<<<BB / 32, 1024>>>(tags);
    crf_pass<<<dim3(32, 64), 128>>>(em, trans, st, en, tags);
    combine_kernel<<<dim3(BB / 32, 2), 1024>>>(en, tags, (float*)d_out);
}